// round 9
// baseline (speedup 1.0000x reference)
#include <cuda_runtime.h>
#include <cuda_bf16.h>
#include <cstdint>
#include <cstddef>

#define BATCH 65536
#define DIN   512
#define HID   1024
#define LAT   64
#define LOG2PI 1.8378770664093453f

typedef __nv_bfloat16 bf16;

// ---------------- scratch (__device__ globals; allocation-free rule) --------
__device__ bf16  sc_xb[(size_t)BATCH * DIN];
__device__ bf16  sc_h [(size_t)BATCH * HID];
__device__ bf16  sc_z [(size_t)BATCH * LAT];
__device__ float sc_kl[BATCH];
__device__ float sc_row[BATCH];
__device__ float sc_part[256];
__device__ bf16  sc_Wt1[(size_t)HID * DIN];
__device__ bf16  sc_Wt2[(size_t)(2*LAT) * HID];
__device__ bf16  sc_Wt3[(size_t)HID * LAT];
__device__ bf16  sc_Wt4[(size_t)(2*DIN) * HID];
__device__ float sc_b2[2*LAT];
__device__ float sc_b4[2*DIN];

// ---------------- helpers ---------------------------------------------------
__device__ __forceinline__ uint32_t smem_u32(const void* p) {
    uint32_t a;
    asm("{ .reg .u64 t; cvta.to.shared.u64 t, %1; cvt.u32.u64 %0, t; }" : "=r"(a) : "l"(p));
    return a;
}
#define SWZ(off) ((off) ^ (((off) >> 3) & 0x70))

__device__ __forceinline__ void cp16(uint32_t dst, const void* src) {
    asm volatile("cp.async.cg.shared.global [%0], [%1], 16;" :: "r"(dst), "l"(src));
}
#define CP_COMMIT() asm volatile("cp.async.commit_group;" ::: "memory")
#define CP_WAIT(n)  asm volatile("cp.async.wait_group %0;" :: "n"(n) : "memory")

__device__ __forceinline__ void ldmA(uint32_t& a0, uint32_t& a1, uint32_t& a2, uint32_t& a3,
                                     uint32_t addr) {
    asm volatile("ldmatrix.sync.aligned.m8n8.x4.shared.b16 {%0,%1,%2,%3}, [%4];"
                 : "=r"(a0), "=r"(a1), "=r"(a2), "=r"(a3) : "r"(addr));
}
__device__ __forceinline__ void ldmB(uint32_t& b0, uint32_t& b1, uint32_t addr) {
    asm volatile("ldmatrix.sync.aligned.m8n8.x2.shared.b16 {%0,%1}, [%2];"
                 : "=r"(b0), "=r"(b1) : "r"(addr));
}
__device__ __forceinline__ void mma16816(float& c0, float& c1, float& c2, float& c3,
                                         uint32_t a0, uint32_t a1, uint32_t a2, uint32_t a3,
                                         uint32_t b0, uint32_t b1) {
    asm volatile("mma.sync.aligned.m16n8k16.row.col.f32.bf16.bf16.f32 "
                 "{%0,%1,%2,%3}, {%4,%5,%6,%7}, {%8,%9}, {%0,%1,%2,%3};"
                 : "+f"(c0), "+f"(c1), "+f"(c2), "+f"(c3)
                 : "r"(a0), "r"(a1), "r"(a2), "r"(a3), "r"(b0), "r"(b1));
}

// ---------------- tile prefetch: 128 rows x 64 bf16, SW128, cp.async --------
__device__ __forceinline__ void prefetch_tile(const bf16* __restrict__ g, int pitch,
                                              int row0, int kofs, uint32_t sbase, int tid) {
#pragma unroll
    for (int u = 0; u < 4; u++) {
        int id  = tid + u * 256;
        int r   = id >> 3;
        int c16 = id & 7;
        uint32_t off = (uint32_t)(r * 128 + c16 * 16);
        cp16(sbase + SWZ(off), g + (size_t)(row0 + r) * pitch + kofs + c16 * 8);
    }
}

// ---------------- mma.sync GEMM (GEMM1/2/3) ---------------------------------
// block tile 128x128, BK=64, 256 threads (8 warps, 2x4), warp tile 64x32.
// EPI: 1 = bias+tanh+bf16 store, 2 = enc head (z, KL)
static constexpr int PAD = 130;
static constexpr int SMEMSZ = PAD * 128 * 4;

template<int EPI>
__global__ __launch_bounds__(256) void gemm_mma(
    const bf16* __restrict__ A, int Ka,
    const bf16* __restrict__ Bt,
    const float* __restrict__ bias,
    void* __restrict__ Cout, int Np,
    const float* __restrict__ eps, bf16* __restrict__ zout, float* __restrict__ klout)
{
    extern __shared__ char smem[];
    const uint32_t sb = smem_u32(smem);
    const int tid = threadIdx.x, wid = tid >> 5, lane = tid & 31;
    const int wm = wid >> 2, wn = wid & 3;
    const int row0 = blockIdx.y * 128, col0 = blockIdx.x * 128;
    const uint32_t SA[2] = { sb, sb + 16384 };
    const uint32_t SB[2] = { sb + 32768, sb + 49152 };

    float c[4][4][4];
#pragma unroll
    for (int i = 0; i < 4; i++)
#pragma unroll
        for (int j = 0; j < 4; j++)
#pragma unroll
            for (int q = 0; q < 4; q++) c[i][j][q] = 0.0f;

    const int KT = Ka / 64;
    prefetch_tile(A,  Ka, row0, 0, SA[0], tid);
    prefetch_tile(Bt, Ka, col0, 0, SB[0], tid);
    CP_COMMIT();

    const int arow = wm * 64 + (lane & 15);
    const uint32_t acol = ((uint32_t)(lane >> 4)) << 4;
    const int brow = wn * 32 + (lane & 7);
    const uint32_t bcol = ((uint32_t)((lane >> 3) & 1)) << 4;

    for (int kt = 0; kt < KT; kt++) {
        const int buf = kt & 1;
        if (kt + 1 < KT) {
            prefetch_tile(A,  Ka, row0, (kt + 1) * 64, SA[buf ^ 1], tid);
            prefetch_tile(Bt, Ka, col0, (kt + 1) * 64, SB[buf ^ 1], tid);
            CP_COMMIT();
            CP_WAIT(1);
        } else {
            CP_WAIT(0);
        }
        __syncthreads();

#pragma unroll
        for (int ks = 0; ks < 4; ks++) {
            uint32_t af[4][4], bfr[4][2];
#pragma unroll
            for (int i = 0; i < 4; i++) {
                uint32_t off = (uint32_t)((arow + i * 16) * 128) + ks * 32 + acol;
                ldmA(af[i][0], af[i][1], af[i][2], af[i][3], SA[buf] + SWZ(off));
            }
#pragma unroll
            for (int j = 0; j < 4; j++) {
                uint32_t off = (uint32_t)((brow + j * 8) * 128) + ks * 32 + bcol;
                ldmB(bfr[j][0], bfr[j][1], SB[buf] + SWZ(off));
            }
#pragma unroll
            for (int i = 0; i < 4; i++)
#pragma unroll
                for (int j = 0; j < 4; j++)
                    mma16816(c[i][j][0], c[i][j][1], c[i][j][2], c[i][j][3],
                             af[i][0], af[i][1], af[i][2], af[i][3],
                             bfr[j][0], bfr[j][1]);
        }
        __syncthreads();
    }

    float* stg = (float*)smem;
    {
        const int r0 = wm * 64 + (lane >> 2);
        const int cfix = wn * 32 + (lane & 3) * 2;
#pragma unroll
        for (int i = 0; i < 4; i++)
#pragma unroll
            for (int j = 0; j < 4; j++) {
                int sr = r0 + i * 16, scol = cfix + j * 8;
                stg[sr * PAD + scol]           = c[i][j][0];
                stg[sr * PAD + scol + 1]       = c[i][j][1];
                stg[(sr + 8) * PAD + scol]     = c[i][j][2];
                stg[(sr + 8) * PAD + scol + 1] = c[i][j][3];
            }
    }
    __syncthreads();

    if (EPI == 2) {
        if (tid < 128) {
            const int row = tid;
            const int r = row0 + row;
            float klacc = 0.0f;
            uint32_t zp[32];
            const float* er = eps + (size_t)r * LAT;
#pragma unroll
            for (int j = 0; j < 64; j += 2) {
                float mu0 = stg[row * PAD + j]     + bias[j];
                float mu1 = stg[row * PAD + j + 1] + bias[j + 1];
                float lv0 = stg[row * PAD + 64 + j]     + bias[64 + j];
                float lv1 = stg[row * PAD + 64 + j + 1] + bias[64 + j + 1];
                float z0 = fmaf(expf(0.5f * lv0), er[j],     mu0);
                float z1 = fmaf(expf(0.5f * lv1), er[j + 1], mu1);
                klacc += (1.0f + lv0 - mu0 * mu0 - expf(lv0));
                klacc += (1.0f + lv1 - mu1 * mu1 - expf(lv1));
                __nv_bfloat162 t = __floats2bfloat162_rn(z0, z1);
                zp[j >> 1] = *(uint32_t*)&t;
            }
            uint4* dst = (uint4*)(zout + (size_t)r * LAT);
#pragma unroll
            for (int q = 0; q < 8; q++) dst[q] = ((uint4*)zp)[q];
            klout[r] = -0.5f * klacc;
        }
    } else {
#pragma unroll
        for (int it = 0; it < 16; it++) {
            int id = tid + it * 256;
            int row = id >> 5, col = (id & 31) * 4;
            float v0 = stg[row * PAD + col]     + bias[col0 + col];
            float v1 = stg[row * PAD + col + 1] + bias[col0 + col + 1];
            float v2 = stg[row * PAD + col + 2] + bias[col0 + col + 2];
            float v3 = stg[row * PAD + col + 3] + bias[col0 + col + 3];
            v0 = tanhf(v0); v1 = tanhf(v1); v2 = tanhf(v2); v3 = tanhf(v3);
            __nv_bfloat162 t0 = __floats2bfloat162_rn(v0, v1);
            __nv_bfloat162 t1 = __floats2bfloat162_rn(v2, v3);
            uint2 o = make_uint2(*(uint32_t*)&t0, *(uint32_t*)&t1);
            *(uint2*)((bf16*)Cout + (size_t)(row0 + row) * Np + col0 + col) = o;
        }
    }
}

// ---------------- fused decoder head: GEMM4 + softmax + likelihood ----------
// One block = 128 rows, sweeps all 8 column tiles (4 mu, 4 lv) of Wt4 [1024,1024].
// mu tiles -> bf16 logits in smem; stats; lv tiles -> terms, row reduction.
static constexpr int LPITCH = 520;                       // bf16 elements per row
static constexpr int LOG_OFF = 65536;                    // tiles below, logits above
static constexpr int ST_OFF  = LOG_OFF + 128 * LPITCH * 2;
static constexpr int FSMEM   = ST_OFF + 2048;            // 256+128+128 floats stats

__global__ __launch_bounds__(256) void dec_fused(
    const bf16* __restrict__ A,        // hd [B,1024]
    const bf16* __restrict__ Bt,       // Wt4 [1024,1024] (mu rows 0..511, lv 512..1023)
    const float* __restrict__ bias,    // b4 [1024]
    const float* __restrict__ x,       // [B,512] fp32
    const float* __restrict__ kl,
    float* __restrict__ rowout)
{
    extern __shared__ char smem[];
    const uint32_t sb = smem_u32(smem);
    bf16*  logits = (bf16*)(smem + LOG_OFF);
    float* tmp    = (float*)(smem + ST_OFF);       // [256]
    float* rowm   = tmp + 256;                     // [128]
    float* rowinv = rowm + 128;                    // [128]
    float* red    = (float*)smem;                  // alias tile area (end only)

    const int tid = threadIdx.x, wid = tid >> 5, lane = tid & 31;
    const int wm = wid >> 2, wn = wid & 3;
    const int row0 = blockIdx.x * 128;
    const uint32_t SA[2] = { sb, sb + 16384 };
    const uint32_t SB[2] = { sb + 32768, sb + 49152 };

    const int arow = wm * 64 + (lane & 15);
    const uint32_t acol = ((uint32_t)(lane >> 4)) << 4;
    const int brow = wn * 32 + (lane & 7);
    const uint32_t bcol = ((uint32_t)((lane >> 3) & 1)) << 4;

    const int fr0 = wm * 64 + (lane >> 2);         // fragment row base
    const int fc0 = wn * 32 + (lane & 3) * 2;      // fragment col base

    float part[4][2];
#pragma unroll
    for (int i = 0; i < 4; i++) { part[i][0] = 0.0f; part[i][1] = 0.0f; }

    for (int nt = 0; nt < 8; nt++) {
        const int col0 = nt * 128;
        float c[4][4][4];
#pragma unroll
        for (int i = 0; i < 4; i++)
#pragma unroll
            for (int j = 0; j < 4; j++)
#pragma unroll
                for (int q = 0; q < 4; q++) c[i][j][q] = 0.0f;

        prefetch_tile(A,  HID, row0, 0, SA[0], tid);
        prefetch_tile(Bt, HID, col0, 0, SB[0], tid);
        CP_COMMIT();

        for (int kt = 0; kt < HID / 64; kt++) {
            const int buf = kt & 1;
            if (kt + 1 < HID / 64) {
                prefetch_tile(A,  HID, row0, (kt + 1) * 64, SA[buf ^ 1], tid);
                prefetch_tile(Bt, HID, col0, (kt + 1) * 64, SB[buf ^ 1], tid);
                CP_COMMIT();
                CP_WAIT(1);
            } else {
                CP_WAIT(0);
            }
            __syncthreads();
#pragma unroll
            for (int ks = 0; ks < 4; ks++) {
                uint32_t af[4][4], bfr[4][2];
#pragma unroll
                for (int i = 0; i < 4; i++) {
                    uint32_t off = (uint32_t)((arow + i * 16) * 128) + ks * 32 + acol;
                    ldmA(af[i][0], af[i][1], af[i][2], af[i][3], SA[buf] + SWZ(off));
                }
#pragma unroll
                for (int j = 0; j < 4; j++) {
                    uint32_t off = (uint32_t)((brow + j * 8) * 128) + ks * 32 + bcol;
                    ldmB(bfr[j][0], bfr[j][1], SB[buf] + SWZ(off));
                }
#pragma unroll
                for (int i = 0; i < 4; i++)
#pragma unroll
                    for (int j = 0; j < 4; j++)
                        mma16816(c[i][j][0], c[i][j][1], c[i][j][2], c[i][j][3],
                                 af[i][0], af[i][1], af[i][2], af[i][3],
                                 bfr[j][0], bfr[j][1]);
            }
            __syncthreads();
        }

        if (nt < 4) {
            // ---- mu tile: bias + store bf16 logits to smem ----
#pragma unroll
            for (int i = 0; i < 4; i++) {
#pragma unroll
                for (int j = 0; j < 4; j++) {
                    int sc = fc0 + j * 8;
                    float b0 = bias[col0 + sc], b1 = bias[col0 + sc + 1];
                    int r0i = fr0 + i * 16;
                    __nv_bfloat162 t0 = __floats2bfloat162_rn(c[i][j][0] + b0, c[i][j][1] + b1);
                    __nv_bfloat162 t1 = __floats2bfloat162_rn(c[i][j][2] + b0, c[i][j][3] + b1);
                    *(uint32_t*)&logits[r0i * LPITCH + col0 + sc]       = *(uint32_t*)&t0;
                    *(uint32_t*)&logits[(r0i + 8) * LPITCH + col0 + sc] = *(uint32_t*)&t1;
                }
            }
            if (nt == 3) {
                // ---- row stats: max then sumexp over 512 bf16 logits ----
                __syncthreads();
                const int row = tid >> 1, half = tid & 1;
                const bf16* lp = logits + row * LPITCH + half * 256;
                float m = -1e30f;
#pragma unroll 8
                for (int q = 0; q < 256; q++) m = fmaxf(m, __bfloat162float(lp[q]));
                tmp[tid] = m;
                __syncthreads();
                if (tid < 128) rowm[tid] = fmaxf(tmp[tid * 2], tmp[tid * 2 + 1]);
                __syncthreads();
                float mm = rowm[row];
                float s = 0.0f;
#pragma unroll 8
                for (int q = 0; q < 256; q++) s += expf(__bfloat162float(lp[q]) - mm);
                tmp[tid] = s;
                __syncthreads();
                if (tid < 128) rowinv[tid] = 1.0f / (tmp[tid * 2] + tmp[tid * 2 + 1]);
                __syncthreads();
            }
        } else {
            // ---- lv tile: term = lv + (x-p)^2 * exp(-lv) ----
            const int lvc0 = col0 - 512;
#pragma unroll
            for (int i = 0; i < 4; i++) {
#pragma unroll
                for (int hv = 0; hv < 2; hv++) {
                    int sr = fr0 + i * 16 + hv * 8;
                    int r = row0 + sr;
                    float mm = rowm[sr], inv = rowinv[sr];
                    float acc = 0.0f;
#pragma unroll
                    for (int j = 0; j < 4; j++) {
                        int gc = lvc0 + fc0 + j * 8;
                        float lv0 = c[i][j][hv * 2]     + bias[512 + gc];
                        float lv1 = c[i][j][hv * 2 + 1] + bias[512 + gc + 1];
                        uint32_t lw = *(uint32_t*)&logits[sr * LPITCH + gc];
                        __nv_bfloat162 lb = *(__nv_bfloat162*)&lw;
                        float p0 = expf(__bfloat162float(lb.x) - mm) * inv;
                        float p1 = expf(__bfloat162float(lb.y) - mm) * inv;
                        float2 xv = *(const float2*)(x + (size_t)r * DIN + gc);
                        float d0 = xv.x - p0, d1 = xv.y - p1;
                        acc += lv0 + d0 * d0 * expf(-lv0);
                        acc += lv1 + d1 * d1 * expf(-lv1);
                    }
                    part[i][hv] += acc;
                }
            }
        }
    }

    // ---- fixed-order row reduction ----
    __syncthreads();
#pragma unroll
    for (int i = 0; i < 4; i++)
#pragma unroll
        for (int hv = 0; hv < 2; hv++) {
            int sr = fr0 + i * 16 + hv * 8;
            red[sr * 16 + wn * 4 + (lane & 3)] = part[i][hv];
        }
    __syncthreads();
    if (tid < 128) {
        float s = 0.0f;
#pragma unroll
        for (int q = 0; q < 16; q++) s += red[tid * 16 + q];
        int r = row0 + tid;
        rowout[r] = -0.5f * (s + (float)DIN * LOG2PI) - kl[r];
    }
}

// ---------------- weight transpose+convert ----------------------------------
__global__ void transpose_w(const float* __restrict__ src, bf16* __restrict__ dst,
                            int Ks, int Ns, int Kd, int n_off) {
    __shared__ float tile[32][33];
    int k0 = blockIdx.x * 32, n0 = blockIdx.y * 32;
    for (int i = threadIdx.y; i < 32; i += 8)
        tile[i][threadIdx.x] = src[(size_t)(k0 + i) * Ns + n0 + threadIdx.x];
    __syncthreads();
    for (int i = threadIdx.y; i < 32; i += 8)
        dst[(size_t)(n_off + n0 + i) * Kd + k0 + threadIdx.x] =
            __float2bfloat16(tile[threadIdx.x][i]);
}

__global__ void concat_bias(const float* __restrict__ a, const float* __restrict__ b,
                            float* __restrict__ d, int n) {
    int i = blockIdx.x * blockDim.x + threadIdx.x;
    if (i < n) d[i] = a[i];
    else if (i < 2 * n) d[i] = b[i - n];
}

__global__ void conv_x(const float* __restrict__ x, bf16* __restrict__ xb) {
    size_t i = ((size_t)blockIdx.x * blockDim.x + threadIdx.x) * 8;
    float4 a = *(const float4*)(x + i);
    float4 b = *(const float4*)(x + i + 4);
    uint32_t p[4];
    __nv_bfloat162 t;
    t = __floats2bfloat162_rn(a.x, a.y); p[0] = *(uint32_t*)&t;
    t = __floats2bfloat162_rn(a.z, a.w); p[1] = *(uint32_t*)&t;
    t = __floats2bfloat162_rn(b.x, b.y); p[2] = *(uint32_t*)&t;
    t = __floats2bfloat162_rn(b.z, b.w); p[3] = *(uint32_t*)&t;
    *(uint4*)(xb + i) = *(uint4*)p;
}

// ---------------- deterministic mean ----------------------------------------
__global__ void reduce_partial(const float* __restrict__ in, float* __restrict__ part) {
    const int t = threadIdx.x;
    __shared__ float sh[8];
    float v = in[blockIdx.x * 256 + t];
#pragma unroll
    for (int o = 16; o > 0; o >>= 1) v += __shfl_xor_sync(0xffffffffu, v, o);
    if ((t & 31) == 0) sh[t >> 5] = v;
    __syncthreads();
    if (t == 0) {
        float s = 0.0f;
#pragma unroll
        for (int w = 0; w < 8; w++) s += sh[w];
        part[blockIdx.x] = s;
    }
}
__global__ void reduce_final(const float* __restrict__ part, float* __restrict__ out) {
    const int t = threadIdx.x;
    __shared__ float sh[8];
    float v = part[t];
#pragma unroll
    for (int o = 16; o > 0; o >>= 1) v += __shfl_xor_sync(0xffffffffu, v, o);
    if ((t & 31) == 0) sh[t >> 5] = v;
    __syncthreads();
    if (t == 0) {
        float s = 0.0f;
#pragma unroll
        for (int w = 0; w < 8; w++) s += sh[w];
        out[0] = s * (1.0f / (float)BATCH);
    }
}

// ---------------- launch ----------------------------------------------------
extern "C" void kernel_launch(void* const* d_in, const int* in_sizes, int n_in,
                              void* d_out, int out_size) {
    const float* x        = (const float*)d_in[0];
    const float* eps      = (const float*)d_in[1];
    const float* W_enc_h  = (const float*)d_in[2];
    const float* b_enc_h  = (const float*)d_in[3];
    const float* W_enc_mu = (const float*)d_in[4];
    const float* b_enc_mu = (const float*)d_in[5];
    const float* W_enc_lv = (const float*)d_in[6];
    const float* b_enc_lv = (const float*)d_in[7];
    const float* W_dec_h  = (const float*)d_in[8];
    const float* b_dec_h  = (const float*)d_in[9];
    const float* W_dec_mu = (const float*)d_in[10];
    const float* b_dec_mu = (const float*)d_in[11];
    const float* W_dec_lv = (const float*)d_in[12];
    const float* b_dec_lv = (const float*)d_in[13];
    float* out = (float*)d_out;

    bf16 *p_xb, *p_h, *p_z, *p_Wt1, *p_Wt2, *p_Wt3, *p_Wt4;
    float *p_kl, *p_row, *p_part, *p_b2, *p_b4;
    cudaGetSymbolAddress((void**)&p_xb, sc_xb);
    cudaGetSymbolAddress((void**)&p_h, sc_h);
    cudaGetSymbolAddress((void**)&p_z, sc_z);
    cudaGetSymbolAddress((void**)&p_kl, sc_kl);
    cudaGetSymbolAddress((void**)&p_row, sc_row);
    cudaGetSymbolAddress((void**)&p_part, sc_part);
    cudaGetSymbolAddress((void**)&p_Wt1, sc_Wt1);
    cudaGetSymbolAddress((void**)&p_Wt2, sc_Wt2);
    cudaGetSymbolAddress((void**)&p_Wt3, sc_Wt3);
    cudaGetSymbolAddress((void**)&p_Wt4, sc_Wt4);
    cudaGetSymbolAddress((void**)&p_b2, sc_b2);
    cudaGetSymbolAddress((void**)&p_b4, sc_b4);

    cudaFuncSetAttribute(gemm_mma<1>, cudaFuncAttributeMaxDynamicSharedMemorySize, SMEMSZ);
    cudaFuncSetAttribute(gemm_mma<2>, cudaFuncAttributeMaxDynamicSharedMemorySize, SMEMSZ);
    cudaFuncSetAttribute(dec_fused,   cudaFuncAttributeMaxDynamicSharedMemorySize, FSMEM);

    // prep
    conv_x<<<(BATCH * DIN) / (256 * 8), 256>>>(x, p_xb);
    transpose_w<<<dim3(16, 32), dim3(32, 8)>>>(W_enc_h,  p_Wt1, 512, 1024, 512, 0);
    transpose_w<<<dim3(32, 2),  dim3(32, 8)>>>(W_enc_mu, p_Wt2, 1024, 64, 1024, 0);
    transpose_w<<<dim3(32, 2),  dim3(32, 8)>>>(W_enc_lv, p_Wt2, 1024, 64, 1024, 64);
    transpose_w<<<dim3(2, 32),  dim3(32, 8)>>>(W_dec_h,  p_Wt3, 64, 1024, 64, 0);
    transpose_w<<<dim3(32, 16), dim3(32, 8)>>>(W_dec_mu, p_Wt4, 1024, 512, 1024, 0);
    transpose_w<<<dim3(32, 16), dim3(32, 8)>>>(W_dec_lv, p_Wt4, 1024, 512, 1024, 512);
    concat_bias<<<1, 128>>>(b_enc_mu, b_enc_lv, p_b2, LAT);
    concat_bias<<<4, 256>>>(b_dec_mu, b_dec_lv, p_b4, DIN);

    // 1) h = tanh(x @ W1)
    gemm_mma<1><<<dim3(8, 512), 256, SMEMSZ>>>(p_xb, DIN, p_Wt1, b_enc_h, p_h, HID,
                                               nullptr, nullptr, nullptr);
    // 2) enc head -> z, kl
    gemm_mma<2><<<dim3(1, 512), 256, SMEMSZ>>>(p_h, HID, p_Wt2, p_b2, nullptr, 0,
                                               eps, p_z, p_kl);
    // 3) hd = tanh(z @ W3)
    gemm_mma<1><<<dim3(8, 512), 256, SMEMSZ>>>(p_z, LAT, p_Wt3, b_dec_h, p_h, HID,
                                               nullptr, nullptr, nullptr);
    // 4) fused: logits|lvx + softmax + likelihood -> rowout
    dec_fused<<<BATCH / 128, 256, FSMEM>>>(p_h, p_Wt4, p_b4, x, p_kl, p_row);
    // 5) deterministic mean
    reduce_partial<<<256, 256>>>(p_row, p_part);
    reduce_final<<<1, 256>>>(p_part, out);
}

// round 11
// speedup vs baseline: 1.6238x; 1.6238x over previous
#include <cuda_runtime.h>
#include <cuda_bf16.h>
#include <cstdint>
#include <cstddef>

#define BATCH 65536
#define DIN   512
#define HID   1024
#define LAT   64
#define LOG2PI 1.8378770664093453f

typedef __nv_bfloat16 bf16;

// ---------------- scratch (__device__ globals; allocation-free rule) --------
__device__ bf16  sc_xb[(size_t)BATCH * DIN];        // x bf16             64MB
__device__ bf16  sc_h [(size_t)BATCH * HID];        // h / hd bf16       128MB
__device__ bf16  sc_z [(size_t)BATCH * LAT];        // z bf16              8MB
__device__ bf16  sc_out4[(size_t)BATCH * (2*DIN)];  // logits|lvx bf16   128MB
__device__ float sc_kl[BATCH];
__device__ float sc_row[BATCH];
__device__ float sc_part[256];
__device__ bf16  sc_Wt1[(size_t)HID * DIN];
__device__ bf16  sc_Wt2[(size_t)(2*LAT) * HID];
__device__ bf16  sc_Wt3[(size_t)HID * LAT];
__device__ bf16  sc_Wt4[(size_t)(2*DIN) * HID];
__device__ float sc_b2[2*LAT];
__device__ float sc_b4[2*DIN];

// ---------------- helpers ---------------------------------------------------
__device__ __forceinline__ uint32_t smem_u32(const void* p) {
    uint32_t a;
    asm("{ .reg .u64 t; cvta.to.shared.u64 t, %1; cvt.u32.u64 %0, t; }" : "=r"(a) : "l"(p));
    return a;
}
#define SWZ(off) ((off) ^ (((off) >> 3) & 0x70))

__device__ __forceinline__ void cp16(uint32_t dst, const void* src) {
    asm volatile("cp.async.cg.shared.global [%0], [%1], 16;" :: "r"(dst), "l"(src));
}
#define CP_COMMIT() asm volatile("cp.async.commit_group;" ::: "memory")
#define CP_WAIT(n)  asm volatile("cp.async.wait_group %0;" :: "n"(n) : "memory")

__device__ __forceinline__ void ldmA(uint32_t& a0, uint32_t& a1, uint32_t& a2, uint32_t& a3,
                                     uint32_t addr) {
    asm volatile("ldmatrix.sync.aligned.m8n8.x4.shared.b16 {%0,%1,%2,%3}, [%4];"
                 : "=r"(a0), "=r"(a1), "=r"(a2), "=r"(a3) : "r"(addr));
}
__device__ __forceinline__ void ldmB(uint32_t& b0, uint32_t& b1, uint32_t addr) {
    asm volatile("ldmatrix.sync.aligned.m8n8.x2.shared.b16 {%0,%1}, [%2];"
                 : "=r"(b0), "=r"(b1) : "r"(addr));
}
__device__ __forceinline__ void mma16816(float& c0, float& c1, float& c2, float& c3,
                                         uint32_t a0, uint32_t a1, uint32_t a2, uint32_t a3,
                                         uint32_t b0, uint32_t b1) {
    asm volatile("mma.sync.aligned.m16n8k16.row.col.f32.bf16.bf16.f32 "
                 "{%0,%1,%2,%3}, {%4,%5,%6,%7}, {%8,%9}, {%0,%1,%2,%3};"
                 : "+f"(c0), "+f"(c1), "+f"(c2), "+f"(c3)
                 : "r"(a0), "r"(a1), "r"(a2), "r"(a3), "r"(b0), "r"(b1));
}

// ---------------- tile prefetch: 128 rows x 64 bf16, SW128, cp.async --------
__device__ __forceinline__ void prefetch_tile(const bf16* __restrict__ g, int pitch,
                                              int row0, int kofs, uint32_t sbase, int tid) {
#pragma unroll
    for (int u = 0; u < 4; u++) {
        int id  = tid + u * 256;
        int r   = id >> 3;
        int c16 = id & 7;
        uint32_t off = (uint32_t)(r * 128 + c16 * 16);
        cp16(sbase + SWZ(off), g + (size_t)(row0 + r) * pitch + kofs + c16 * 8);
    }
}

// ---------------- mma.sync GEMM: D = A[M,K] @ Bt[N,K]^T ---------------------
// block tile 128x128, BK=64, 256 threads (8 warps, 2x4), warp tile 64x32.
// EPI: 0 = bias + bf16 store, 1 = bias+tanh+bf16 store, 2 = enc head (z, KL)
static constexpr int PAD = 130;
static constexpr int SMEMSZ = PAD * 128 * 4;

template<int EPI>
__global__ __launch_bounds__(256) void gemm_mma(
    const bf16* __restrict__ A, int Ka,
    const bf16* __restrict__ Bt,
    const float* __restrict__ bias,
    void* __restrict__ Cout, int Np,
    const float* __restrict__ eps, bf16* __restrict__ zout, float* __restrict__ klout)
{
    extern __shared__ char smem[];
    const uint32_t sb = smem_u32(smem);
    const int tid = threadIdx.x, wid = tid >> 5, lane = tid & 31;
    const int wm = wid >> 2, wn = wid & 3;
    const int row0 = blockIdx.y * 128, col0 = blockIdx.x * 128;
    const uint32_t SA[2] = { sb, sb + 16384 };
    const uint32_t SB[2] = { sb + 32768, sb + 49152 };

    float c[4][4][4];
#pragma unroll
    for (int i = 0; i < 4; i++)
#pragma unroll
        for (int j = 0; j < 4; j++)
#pragma unroll
            for (int q = 0; q < 4; q++) c[i][j][q] = 0.0f;

    const int KT = Ka / 64;
    prefetch_tile(A,  Ka, row0, 0, SA[0], tid);
    prefetch_tile(Bt, Ka, col0, 0, SB[0], tid);
    CP_COMMIT();

    const int arow = wm * 64 + (lane & 15);
    const uint32_t acol = ((uint32_t)(lane >> 4)) << 4;
    const int brow = wn * 32 + (lane & 7);
    const uint32_t bcol = ((uint32_t)((lane >> 3) & 1)) << 4;

    for (int kt = 0; kt < KT; kt++) {
        const int buf = kt & 1;
        if (kt + 1 < KT) {
            prefetch_tile(A,  Ka, row0, (kt + 1) * 64, SA[buf ^ 1], tid);
            prefetch_tile(Bt, Ka, col0, (kt + 1) * 64, SB[buf ^ 1], tid);
            CP_COMMIT();
            CP_WAIT(1);
        } else {
            CP_WAIT(0);
        }
        __syncthreads();

#pragma unroll
        for (int ks = 0; ks < 4; ks++) {
            uint32_t af[4][4], bfr[4][2];
#pragma unroll
            for (int i = 0; i < 4; i++) {
                uint32_t off = (uint32_t)((arow + i * 16) * 128) + ks * 32 + acol;
                ldmA(af[i][0], af[i][1], af[i][2], af[i][3], SA[buf] + SWZ(off));
            }
#pragma unroll
            for (int j = 0; j < 4; j++) {
                uint32_t off = (uint32_t)((brow + j * 8) * 128) + ks * 32 + bcol;
                ldmB(bfr[j][0], bfr[j][1], SB[buf] + SWZ(off));
            }
#pragma unroll
            for (int i = 0; i < 4; i++)
#pragma unroll
                for (int j = 0; j < 4; j++)
                    mma16816(c[i][j][0], c[i][j][1], c[i][j][2], c[i][j][3],
                             af[i][0], af[i][1], af[i][2], af[i][3],
                             bfr[j][0], bfr[j][1]);
        }
        __syncthreads();
    }

    // ---- stage accumulators to padded smem ----
    float* stg = (float*)smem;
    {
        const int r0 = wm * 64 + (lane >> 2);
        const int cfix = wn * 32 + (lane & 3) * 2;
#pragma unroll
        for (int i = 0; i < 4; i++)
#pragma unroll
            for (int j = 0; j < 4; j++) {
                int sr = r0 + i * 16, scol = cfix + j * 8;
                stg[sr * PAD + scol]           = c[i][j][0];
                stg[sr * PAD + scol + 1]       = c[i][j][1];
                stg[(sr + 8) * PAD + scol]     = c[i][j][2];
                stg[(sr + 8) * PAD + scol + 1] = c[i][j][3];
            }
    }
    __syncthreads();

    if (EPI == 2) {
        if (tid < 128) {
            const int row = tid;
            const int r = row0 + row;
            float klacc = 0.0f;
            uint32_t zp[32];
            const float* er = eps + (size_t)r * LAT;
#pragma unroll
            for (int j = 0; j < 64; j += 2) {
                float mu0 = stg[row * PAD + j]     + bias[j];
                float mu1 = stg[row * PAD + j + 1] + bias[j + 1];
                float lv0 = stg[row * PAD + 64 + j]     + bias[64 + j];
                float lv1 = stg[row * PAD + 64 + j + 1] + bias[64 + j + 1];
                float z0 = fmaf(expf(0.5f * lv0), er[j],     mu0);
                float z1 = fmaf(expf(0.5f * lv1), er[j + 1], mu1);
                klacc += (1.0f + lv0 - mu0 * mu0 - expf(lv0));
                klacc += (1.0f + lv1 - mu1 * mu1 - expf(lv1));
                __nv_bfloat162 t = __floats2bfloat162_rn(z0, z1);
                zp[j >> 1] = *(uint32_t*)&t;
            }
            uint4* dst = (uint4*)(zout + (size_t)r * LAT);
#pragma unroll
            for (int q = 0; q < 8; q++) dst[q] = ((uint4*)zp)[q];
            klout[r] = -0.5f * klacc;
        }
    } else {
#pragma unroll
        for (int it = 0; it < 16; it++) {
            int id = tid + it * 256;
            int row = id >> 5, col = (id & 31) * 4;
            float v0 = stg[row * PAD + col]     + bias[col0 + col];
            float v1 = stg[row * PAD + col + 1] + bias[col0 + col + 1];
            float v2 = stg[row * PAD + col + 2] + bias[col0 + col + 2];
            float v3 = stg[row * PAD + col + 3] + bias[col0 + col + 3];
            if (EPI == 1) { v0 = tanhf(v0); v1 = tanhf(v1); v2 = tanhf(v2); v3 = tanhf(v3); }
            __nv_bfloat162 t0 = __floats2bfloat162_rn(v0, v1);
            __nv_bfloat162 t1 = __floats2bfloat162_rn(v2, v3);
            uint2 o = make_uint2(*(uint32_t*)&t0, *(uint32_t*)&t1);
            *(uint2*)((bf16*)Cout + (size_t)(row0 + row) * Np + col0 + col) = o;
        }
    }
}

// ---------------- weight transpose+convert ----------------------------------
__global__ void transpose_w(const float* __restrict__ src, bf16* __restrict__ dst,
                            int Ks, int Ns, int Kd, int n_off) {
    __shared__ float tile[32][33];
    int k0 = blockIdx.x * 32, n0 = blockIdx.y * 32;
    for (int i = threadIdx.y; i < 32; i += 8)
        tile[i][threadIdx.x] = src[(size_t)(k0 + i) * Ns + n0 + threadIdx.x];
    __syncthreads();
    for (int i = threadIdx.y; i < 32; i += 8)
        dst[(size_t)(n_off + n0 + i) * Kd + k0 + threadIdx.x] =
            __float2bfloat16(tile[threadIdx.x][i]);
}

__global__ void concat_bias(const float* __restrict__ a, const float* __restrict__ b,
                            float* __restrict__ d, int n) {
    int i = blockIdx.x * blockDim.x + threadIdx.x;
    if (i < n) d[i] = a[i];
    else if (i < 2 * n) d[i] = b[i - n];
}

__global__ void conv_x(const float* __restrict__ x, bf16* __restrict__ xb) {
    size_t i = ((size_t)blockIdx.x * blockDim.x + threadIdx.x) * 8;
    float4 a = *(const float4*)(x + i);
    float4 b = *(const float4*)(x + i + 4);
    uint32_t p[4];
    __nv_bfloat162 t;
    t = __floats2bfloat162_rn(a.x, a.y); p[0] = *(uint32_t*)&t;
    t = __floats2bfloat162_rn(a.z, a.w); p[1] = *(uint32_t*)&t;
    t = __floats2bfloat162_rn(b.x, b.y); p[2] = *(uint32_t*)&t;
    t = __floats2bfloat162_rn(b.z, b.w); p[3] = *(uint32_t*)&t;
    *(uint4*)(xb + i) = *(uint4*)p;
}

// ---------------- per-row softmax + likelihood (bf16 logits/lvx) ------------
__global__ void row_loss(const bf16* __restrict__ out4, const float* __restrict__ x,
                         const float* __restrict__ kl, float* __restrict__ rowout) {
    const int row = blockIdx.x;
    const int t = threadIdx.x;
    __shared__ float sh[8];
    const bf16* lr = out4 + (size_t)row * (2 * DIN);
    const bf16* vr = lr + DIN;
    float l0 = __bfloat162float(lr[t]), l1 = __bfloat162float(lr[t + 256]);

    float m = fmaxf(l0, l1);
#pragma unroll
    for (int o = 16; o > 0; o >>= 1) m = fmaxf(m, __shfl_xor_sync(0xffffffffu, m, o));
    if ((t & 31) == 0) sh[t >> 5] = m;
    __syncthreads();
    m = sh[0];
#pragma unroll
    for (int w = 1; w < 8; w++) m = fmaxf(m, sh[w]);
    __syncthreads();

    float e0 = expf(l0 - m), e1 = expf(l1 - m);
    float s = e0 + e1;
#pragma unroll
    for (int o = 16; o > 0; o >>= 1) s += __shfl_xor_sync(0xffffffffu, s, o);
    if ((t & 31) == 0) sh[t >> 5] = s;
    __syncthreads();
    s = 0.0f;
#pragma unroll
    for (int w = 0; w < 8; w++) s += sh[w];
    __syncthreads();
    float inv = 1.0f / s;

    const float* xr = x + (size_t)row * DIN;
    float acc = 0.0f;
    {
        float p = e0 * inv, xv = xr[t];
        float lv = __bfloat162float(vr[t]);
        float d = xv - p;
        acc += lv + d * d * expf(-lv);
        p = e1 * inv; xv = xr[t + 256];
        lv = __bfloat162float(vr[t + 256]);
        d = xv - p;
        acc += lv + d * d * expf(-lv);
    }
#pragma unroll
    for (int o = 16; o > 0; o >>= 1) acc += __shfl_xor_sync(0xffffffffu, acc, o);
    if ((t & 31) == 0) sh[t >> 5] = acc;
    __syncthreads();
    if (t == 0) {
        float tot = 0.0f;
#pragma unroll
        for (int w = 0; w < 8; w++) tot += sh[w];
        float ln_pxz = -0.5f * (tot + (float)DIN * LOG2PI);
        rowout[row] = ln_pxz - kl[row];
    }
}

// ---------------- deterministic mean ----------------------------------------
__global__ void reduce_partial(const float* __restrict__ in, float* __restrict__ part) {
    const int t = threadIdx.x;
    __shared__ float sh[8];
    float v = in[blockIdx.x * 256 + t];
#pragma unroll
    for (int o = 16; o > 0; o >>= 1) v += __shfl_xor_sync(0xffffffffu, v, o);
    if ((t & 31) == 0) sh[t >> 5] = v;
    __syncthreads();
    if (t == 0) {
        float s = 0.0f;
#pragma unroll
        for (int w = 0; w < 8; w++) s += sh[w];
        part[blockIdx.x] = s;
    }
}
__global__ void reduce_final(const float* __restrict__ part, float* __restrict__ out) {
    const int t = threadIdx.x;
    __shared__ float sh[8];
    float v = part[t];
#pragma unroll
    for (int o = 16; o > 0; o >>= 1) v += __shfl_xor_sync(0xffffffffu, v, o);
    if ((t & 31) == 0) sh[t >> 5] = v;
    __syncthreads();
    if (t == 0) {
        float s = 0.0f;
#pragma unroll
        for (int w = 0; w < 8; w++) s += sh[w];
        out[0] = s * (1.0f / (float)BATCH);
    }
}

// ---------------- launch ----------------------------------------------------
extern "C" void kernel_launch(void* const* d_in, const int* in_sizes, int n_in,
                              void* d_out, int out_size) {
    const float* x        = (const float*)d_in[0];
    const float* eps      = (const float*)d_in[1];
    const float* W_enc_h  = (const float*)d_in[2];
    const float* b_enc_h  = (const float*)d_in[3];
    const float* W_enc_mu = (const float*)d_in[4];
    const float* b_enc_mu = (const float*)d_in[5];
    const float* W_enc_lv = (const float*)d_in[6];
    const float* b_enc_lv = (const float*)d_in[7];
    const float* W_dec_h  = (const float*)d_in[8];
    const float* b_dec_h  = (const float*)d_in[9];
    const float* W_dec_mu = (const float*)d_in[10];
    const float* b_dec_mu = (const float*)d_in[11];
    const float* W_dec_lv = (const float*)d_in[12];
    const float* b_dec_lv = (const float*)d_in[13];
    float* out = (float*)d_out;

    bf16 *p_xb, *p_h, *p_z, *p_out4, *p_Wt1, *p_Wt2, *p_Wt3, *p_Wt4;
    float *p_kl, *p_row, *p_part, *p_b2, *p_b4;
    cudaGetSymbolAddress((void**)&p_xb, sc_xb);
    cudaGetSymbolAddress((void**)&p_h, sc_h);
    cudaGetSymbolAddress((void**)&p_z, sc_z);
    cudaGetSymbolAddress((void**)&p_out4, sc_out4);
    cudaGetSymbolAddress((void**)&p_kl, sc_kl);
    cudaGetSymbolAddress((void**)&p_row, sc_row);
    cudaGetSymbolAddress((void**)&p_part, sc_part);
    cudaGetSymbolAddress((void**)&p_Wt1, sc_Wt1);
    cudaGetSymbolAddress((void**)&p_Wt2, sc_Wt2);
    cudaGetSymbolAddress((void**)&p_Wt3, sc_Wt3);
    cudaGetSymbolAddress((void**)&p_Wt4, sc_Wt4);
    cudaGetSymbolAddress((void**)&p_b2, sc_b2);
    cudaGetSymbolAddress((void**)&p_b4, sc_b4);

    cudaFuncSetAttribute(gemm_mma<0>, cudaFuncAttributeMaxDynamicSharedMemorySize, SMEMSZ);
    cudaFuncSetAttribute(gemm_mma<1>, cudaFuncAttributeMaxDynamicSharedMemorySize, SMEMSZ);
    cudaFuncSetAttribute(gemm_mma<2>, cudaFuncAttributeMaxDynamicSharedMemorySize, SMEMSZ);

    // prep
    conv_x<<<(BATCH * DIN) / (256 * 8), 256>>>(x, p_xb);
    transpose_w<<<dim3(16, 32), dim3(32, 8)>>>(W_enc_h,  p_Wt1, 512, 1024, 512, 0);
    transpose_w<<<dim3(32, 2),  dim3(32, 8)>>>(W_enc_mu, p_Wt2, 1024, 64, 1024, 0);
    transpose_w<<<dim3(32, 2),  dim3(32, 8)>>>(W_enc_lv, p_Wt2, 1024, 64, 1024, 64);
    transpose_w<<<dim3(2, 32),  dim3(32, 8)>>>(W_dec_h,  p_Wt3, 64, 1024, 64, 0);
    transpose_w<<<dim3(32, 16), dim3(32, 8)>>>(W_dec_mu, p_Wt4, 1024, 512, 1024, 0);
    transpose_w<<<dim3(32, 16), dim3(32, 8)>>>(W_dec_lv, p_Wt4, 1024, 512, 1024, 512);
    concat_bias<<<1, 128>>>(b_enc_mu, b_enc_lv, p_b2, LAT);
    concat_bias<<<4, 256>>>(b_dec_mu, b_dec_lv, p_b4, DIN);

    // 1) h = tanh(x @ W1)
    gemm_mma<1><<<dim3(8, 512), 256, SMEMSZ>>>(p_xb, DIN, p_Wt1, b_enc_h, p_h, HID,
                                               nullptr, nullptr, nullptr);
    // 2) enc head -> z, kl
    gemm_mma<2><<<dim3(1, 512), 256, SMEMSZ>>>(p_h, HID, p_Wt2, p_b2, nullptr, 0,
                                               eps, p_z, p_kl);
    // 3) hd = tanh(z @ W3)
    gemm_mma<1><<<dim3(8, 512), 256, SMEMSZ>>>(p_z, LAT, p_Wt3, b_dec_h, p_h, HID,
                                               nullptr, nullptr, nullptr);
    // 4) logits|lvx = hd @ W4 (bf16 out)
    gemm_mma<0><<<dim3(8, 512), 256, SMEMSZ>>>(p_h, HID, p_Wt4, p_b4, p_out4, 2 * DIN,
                                               nullptr, nullptr, nullptr);
    // 5) per-row loss, 6) deterministic mean
    row_loss<<<BATCH, 256>>>(p_out4, x, p_kl, p_row);
    reduce_partial<<<256, 256>>>(p_row, p_part);
    reduce_final<<<1, 256>>>(p_part, out);
}

// round 12
// speedup vs baseline: 1.7591x; 1.0833x over previous
#include <cuda_runtime.h>
#include <cuda_bf16.h>
#include <cstdint>
#include <cstddef>

#define BATCH 65536
#define DIN   512
#define HID   1024
#define LAT   64
#define LOG2PI 1.8378770664093453f

typedef __nv_bfloat16 bf16;

// ---------------- scratch (__device__ globals; allocation-free rule) --------
__device__ bf16  sc_xb[(size_t)BATCH * DIN];        // x bf16             64MB
__device__ bf16  sc_h [(size_t)BATCH * HID];        // h / hd bf16       128MB
__device__ bf16  sc_z [(size_t)BATCH * LAT];        // z bf16              8MB
__device__ bf16  sc_out4[(size_t)BATCH * (2*DIN)];  // logits|lvx bf16   128MB
__device__ float sc_kl[BATCH];
__device__ float sc_row[BATCH];
__device__ float sc_part[256];
__device__ bf16  sc_Wt1[(size_t)HID * DIN];
__device__ bf16  sc_Wt2[(size_t)(2*LAT) * HID];
__device__ bf16  sc_Wt3[(size_t)HID * LAT];
__device__ bf16  sc_Wt4[(size_t)(2*DIN) * HID];
__device__ float sc_b2[2*LAT];
__device__ float sc_b4[2*DIN];

// ---------------- helpers ---------------------------------------------------
__device__ __forceinline__ uint32_t smem_u32(const void* p) {
    uint32_t a;
    asm("{ .reg .u64 t; cvta.to.shared.u64 t, %1; cvt.u32.u64 %0, t; }" : "=r"(a) : "l"(p));
    return a;
}
#define SWZ(off) ((off) ^ (((off) >> 3) & 0x70))

__device__ __forceinline__ void cp16(uint32_t dst, const void* src) {
    asm volatile("cp.async.cg.shared.global [%0], [%1], 16;" :: "r"(dst), "l"(src));
}
#define CP_COMMIT() asm volatile("cp.async.commit_group;" ::: "memory")
#define CP_WAIT(n)  asm volatile("cp.async.wait_group %0;" :: "n"(n) : "memory")

__device__ __forceinline__ void ldmA(uint32_t& a0, uint32_t& a1, uint32_t& a2, uint32_t& a3,
                                     uint32_t addr) {
    asm volatile("ldmatrix.sync.aligned.m8n8.x4.shared.b16 {%0,%1,%2,%3}, [%4];"
                 : "=r"(a0), "=r"(a1), "=r"(a2), "=r"(a3) : "r"(addr));
}
__device__ __forceinline__ void ldmB(uint32_t& b0, uint32_t& b1, uint32_t addr) {
    asm volatile("ldmatrix.sync.aligned.m8n8.x2.shared.b16 {%0,%1}, [%2];"
                 : "=r"(b0), "=r"(b1) : "r"(addr));
}
__device__ __forceinline__ void mma16816(float& c0, float& c1, float& c2, float& c3,
                                         uint32_t a0, uint32_t a1, uint32_t a2, uint32_t a3,
                                         uint32_t b0, uint32_t b1) {
    asm volatile("mma.sync.aligned.m16n8k16.row.col.f32.bf16.bf16.f32 "
                 "{%0,%1,%2,%3}, {%4,%5,%6,%7}, {%8,%9}, {%0,%1,%2,%3};"
                 : "+f"(c0), "+f"(c1), "+f"(c2), "+f"(c3)
                 : "r"(a0), "r"(a1), "r"(a2), "r"(a3), "r"(b0), "r"(b1));
}

// ---------------- tile prefetch: 128 rows x 64 bf16, SW128, cp.async --------
__device__ __forceinline__ void prefetch_tile(const bf16* __restrict__ g, int pitch,
                                              int row0, int kofs, uint32_t sbase, int tid) {
#pragma unroll
    for (int u = 0; u < 4; u++) {
        int id  = tid + u * 256;
        int r   = id >> 3;
        int c16 = id & 7;
        uint32_t off = (uint32_t)(r * 128 + c16 * 16);
        cp16(sbase + SWZ(off), g + (size_t)(row0 + r) * pitch + kofs + c16 * 8);
    }
}

// ---------------- mma.sync GEMM: D = A[M,K] @ Bt[N,K]^T ---------------------
// block tile 128x128, BK=64, 256 threads (8 warps, 2x4), warp tile 64x32.
// 3-stage cp.async ring, ONE barrier per K-iteration, 2 CTAs/SM enforced.
// EPI: 0 = bias + bf16 store, 1 = bias+tanh+bf16 store, 2 = enc head (z, KL)
static constexpr int PAD = 130;
static constexpr int STAGE = 32768;           // 16KB A + 16KB B per stage
static constexpr int SMEMSZ = 3 * STAGE;      // 98304 -> 2 CTAs/SM

template<int EPI>
__global__ __launch_bounds__(256, 2) void gemm_mma(
    const bf16* __restrict__ A, int Ka,
    const bf16* __restrict__ Bt,
    const float* __restrict__ bias,
    void* __restrict__ Cout, int Np,
    const float* __restrict__ eps, bf16* __restrict__ zout, float* __restrict__ klout)
{
    extern __shared__ char smem[];
    const uint32_t sb = smem_u32(smem);
    const int tid = threadIdx.x, wid = tid >> 5, lane = tid & 31;
    const int wm = wid >> 2, wn = wid & 3;
    const int row0 = blockIdx.y * 128, col0 = blockIdx.x * 128;

    float c[4][4][4];
#pragma unroll
    for (int i = 0; i < 4; i++)
#pragma unroll
        for (int j = 0; j < 4; j++)
#pragma unroll
            for (int q = 0; q < 4; q++) c[i][j][q] = 0.0f;

    const int KT = Ka / 64;
    // prologue: stages 0 and 1 (always two commits so group math is uniform)
    prefetch_tile(A,  Ka, row0, 0, sb, tid);
    prefetch_tile(Bt, Ka, col0, 0, sb + 16384, tid);
    CP_COMMIT();
    if (KT > 1) {
        prefetch_tile(A,  Ka, row0, 64, sb + STAGE, tid);
        prefetch_tile(Bt, Ka, col0, 64, sb + STAGE + 16384, tid);
    }
    CP_COMMIT();

    const int arow = wm * 64 + (lane & 15);
    const uint32_t acol = ((uint32_t)(lane >> 4)) << 4;
    const int brow = wn * 32 + (lane & 7);
    const uint32_t bcol = ((uint32_t)((lane >> 3) & 1)) << 4;

    int stage = 0;
    for (int kt = 0; kt < KT; kt++) {
        CP_WAIT(1);                      // group kt complete (kt+1 still in flight)
        __syncthreads();                 // single barrier per iteration
        {
            // prefetch stage kt+2 (ring slot reused 3 iters later -> safe post-barrier)
            int pf = kt + 2;
            int pstage = stage + 2; if (pstage >= 3) pstage -= 3;
            if (pf < KT) {
                prefetch_tile(A,  Ka, row0, pf * 64, sb + pstage * STAGE, tid);
                prefetch_tile(Bt, Ka, col0, pf * 64, sb + pstage * STAGE + 16384, tid);
            }
            CP_COMMIT();
        }
        const uint32_t SAb = sb + stage * STAGE;
        const uint32_t SBb = SAb + 16384;
#pragma unroll
        for (int ks = 0; ks < 4; ks++) {
            uint32_t af[4][4], bfr[4][2];
#pragma unroll
            for (int i = 0; i < 4; i++) {
                uint32_t off = (uint32_t)((arow + i * 16) * 128) + ks * 32 + acol;
                ldmA(af[i][0], af[i][1], af[i][2], af[i][3], SAb + SWZ(off));
            }
#pragma unroll
            for (int j = 0; j < 4; j++) {
                uint32_t off = (uint32_t)((brow + j * 8) * 128) + ks * 32 + bcol;
                ldmB(bfr[j][0], bfr[j][1], SBb + SWZ(off));
            }
#pragma unroll
            for (int i = 0; i < 4; i++)
#pragma unroll
                for (int j = 0; j < 4; j++)
                    mma16816(c[i][j][0], c[i][j][1], c[i][j][2], c[i][j][3],
                             af[i][0], af[i][1], af[i][2], af[i][3],
                             bfr[j][0], bfr[j][1]);
        }
        if (++stage == 3) stage = 0;
    }

    // ---- stage accumulators to padded smem (reuses ring buffers) ----
    __syncthreads();
    float* stg = (float*)smem;
    {
        const int r0 = wm * 64 + (lane >> 2);
        const int cfix = wn * 32 + (lane & 3) * 2;
#pragma unroll
        for (int i = 0; i < 4; i++)
#pragma unroll
            for (int j = 0; j < 4; j++) {
                int sr = r0 + i * 16, scol = cfix + j * 8;
                stg[sr * PAD + scol]           = c[i][j][0];
                stg[sr * PAD + scol + 1]       = c[i][j][1];
                stg[(sr + 8) * PAD + scol]     = c[i][j][2];
                stg[(sr + 8) * PAD + scol + 1] = c[i][j][3];
            }
    }
    __syncthreads();

    if (EPI == 2) {
        if (tid < 128) {
            const int row = tid;
            const int r = row0 + row;
            float klacc = 0.0f;
            uint32_t zp[32];
            const float* er = eps + (size_t)r * LAT;
#pragma unroll
            for (int j = 0; j < 64; j += 2) {
                float mu0 = stg[row * PAD + j]     + bias[j];
                float mu1 = stg[row * PAD + j + 1] + bias[j + 1];
                float lv0 = stg[row * PAD + 64 + j]     + bias[64 + j];
                float lv1 = stg[row * PAD + 64 + j + 1] + bias[64 + j + 1];
                float z0 = fmaf(expf(0.5f * lv0), er[j],     mu0);
                float z1 = fmaf(expf(0.5f * lv1), er[j + 1], mu1);
                klacc += (1.0f + lv0 - mu0 * mu0 - expf(lv0));
                klacc += (1.0f + lv1 - mu1 * mu1 - expf(lv1));
                __nv_bfloat162 t = __floats2bfloat162_rn(z0, z1);
                zp[j >> 1] = *(uint32_t*)&t;
            }
            uint4* dst = (uint4*)(zout + (size_t)r * LAT);
#pragma unroll
            for (int q = 0; q < 8; q++) dst[q] = ((uint4*)zp)[q];
            klout[r] = -0.5f * klacc;
        }
    } else {
#pragma unroll
        for (int it = 0; it < 16; it++) {
            int id = tid + it * 256;
            int row = id >> 5, col = (id & 31) * 4;
            float v0 = stg[row * PAD + col]     + bias[col0 + col];
            float v1 = stg[row * PAD + col + 1] + bias[col0 + col + 1];
            float v2 = stg[row * PAD + col + 2] + bias[col0 + col + 2];
            float v3 = stg[row * PAD + col + 3] + bias[col0 + col + 3];
            if (EPI == 1) { v0 = tanhf(v0); v1 = tanhf(v1); v2 = tanhf(v2); v3 = tanhf(v3); }
            __nv_bfloat162 t0 = __floats2bfloat162_rn(v0, v1);
            __nv_bfloat162 t1 = __floats2bfloat162_rn(v2, v3);
            uint2 o = make_uint2(*(uint32_t*)&t0, *(uint32_t*)&t1);
            *(uint2*)((bf16*)Cout + (size_t)(row0 + row) * Np + col0 + col) = o;
        }
    }
}

// ---------------- weight transpose+convert ----------------------------------
__global__ void transpose_w(const float* __restrict__ src, bf16* __restrict__ dst,
                            int Ks, int Ns, int Kd, int n_off) {
    __shared__ float tile[32][33];
    int k0 = blockIdx.x * 32, n0 = blockIdx.y * 32;
    for (int i = threadIdx.y; i < 32; i += 8)
        tile[i][threadIdx.x] = src[(size_t)(k0 + i) * Ns + n0 + threadIdx.x];
    __syncthreads();
    for (int i = threadIdx.y; i < 32; i += 8)
        dst[(size_t)(n_off + n0 + i) * Kd + k0 + threadIdx.x] =
            __float2bfloat16(tile[threadIdx.x][i]);
}

__global__ void concat_bias(const float* __restrict__ a, const float* __restrict__ b,
                            float* __restrict__ d, int n) {
    int i = blockIdx.x * blockDim.x + threadIdx.x;
    if (i < n) d[i] = a[i];
    else if (i < 2 * n) d[i] = b[i - n];
}

__global__ void conv_x(const float* __restrict__ x, bf16* __restrict__ xb) {
    size_t i = ((size_t)blockIdx.x * blockDim.x + threadIdx.x) * 8;
    float4 a = *(const float4*)(x + i);
    float4 b = *(const float4*)(x + i + 4);
    uint32_t p[4];
    __nv_bfloat162 t;
    t = __floats2bfloat162_rn(a.x, a.y); p[0] = *(uint32_t*)&t;
    t = __floats2bfloat162_rn(a.z, a.w); p[1] = *(uint32_t*)&t;
    t = __floats2bfloat162_rn(b.x, b.y); p[2] = *(uint32_t*)&t;
    t = __floats2bfloat162_rn(b.z, b.w); p[3] = *(uint32_t*)&t;
    *(uint4*)(xb + i) = *(uint4*)p;
}

// ---------------- per-row softmax + likelihood (bf16 logits/lvx) ------------
__global__ void row_loss(const bf16* __restrict__ out4, const float* __restrict__ x,
                         const float* __restrict__ kl, float* __restrict__ rowout) {
    const int row = blockIdx.x;
    const int t = threadIdx.x;
    __shared__ float sh[8];
    const bf16* lr = out4 + (size_t)row * (2 * DIN);
    const bf16* vr = lr + DIN;
    float l0 = __bfloat162float(lr[t]), l1 = __bfloat162float(lr[t + 256]);

    float m = fmaxf(l0, l1);
#pragma unroll
    for (int o = 16; o > 0; o >>= 1) m = fmaxf(m, __shfl_xor_sync(0xffffffffu, m, o));
    if ((t & 31) == 0) sh[t >> 5] = m;
    __syncthreads();
    m = sh[0];
#pragma unroll
    for (int w = 1; w < 8; w++) m = fmaxf(m, sh[w]);
    __syncthreads();

    float e0 = expf(l0 - m), e1 = expf(l1 - m);
    float s = e0 + e1;
#pragma unroll
    for (int o = 16; o > 0; o >>= 1) s += __shfl_xor_sync(0xffffffffu, s, o);
    if ((t & 31) == 0) sh[t >> 5] = s;
    __syncthreads();
    s = 0.0f;
#pragma unroll
    for (int w = 0; w < 8; w++) s += sh[w];
    __syncthreads();
    float inv = 1.0f / s;

    const float* xr = x + (size_t)row * DIN;
    float acc = 0.0f;
    {
        float p = e0 * inv, xv = xr[t];
        float lv = __bfloat162float(vr[t]);
        float d = xv - p;
        acc += lv + d * d * expf(-lv);
        p = e1 * inv; xv = xr[t + 256];
        lv = __bfloat162float(vr[t + 256]);
        d = xv - p;
        acc += lv + d * d * expf(-lv);
    }
#pragma unroll
    for (int o = 16; o > 0; o >>= 1) acc += __shfl_xor_sync(0xffffffffu, acc, o);
    if ((t & 31) == 0) sh[t >> 5] = acc;
    __syncthreads();
    if (t == 0) {
        float tot = 0.0f;
#pragma unroll
        for (int w = 0; w < 8; w++) tot += sh[w];
        float ln_pxz = -0.5f * (tot + (float)DIN * LOG2PI);
        rowout[row] = ln_pxz - kl[row];
    }
}

// ---------------- deterministic mean ----------------------------------------
__global__ void reduce_partial(const float* __restrict__ in, float* __restrict__ part) {
    const int t = threadIdx.x;
    __shared__ float sh[8];
    float v = in[blockIdx.x * 256 + t];
#pragma unroll
    for (int o = 16; o > 0; o >>= 1) v += __shfl_xor_sync(0xffffffffu, v, o);
    if ((t & 31) == 0) sh[t >> 5] = v;
    __syncthreads();
    if (t == 0) {
        float s = 0.0f;
#pragma unroll
        for (int w = 0; w < 8; w++) s += sh[w];
        part[blockIdx.x] = s;
    }
}
__global__ void reduce_final(const float* __restrict__ part, float* __restrict__ out) {
    const int t = threadIdx.x;
    __shared__ float sh[8];
    float v = part[t];
#pragma unroll
    for (int o = 16; o > 0; o >>= 1) v += __shfl_xor_sync(0xffffffffu, v, o);
    if ((t & 31) == 0) sh[t >> 5] = v;
    __syncthreads();
    if (t == 0) {
        float s = 0.0f;
#pragma unroll
        for (int w = 0; w < 8; w++) s += sh[w];
        out[0] = s * (1.0f / (float)BATCH);
    }
}

// ---------------- launch ----------------------------------------------------
extern "C" void kernel_launch(void* const* d_in, const int* in_sizes, int n_in,
                              void* d_out, int out_size) {
    const float* x        = (const float*)d_in[0];
    const float* eps      = (const float*)d_in[1];
    const float* W_enc_h  = (const float*)d_in[2];
    const float* b_enc_h  = (const float*)d_in[3];
    const float* W_enc_mu = (const float*)d_in[4];
    const float* b_enc_mu = (const float*)d_in[5];
    const float* W_enc_lv = (const float*)d_in[6];
    const float* b_enc_lv = (const float*)d_in[7];
    const float* W_dec_h  = (const float*)d_in[8];
    const float* b_dec_h  = (const float*)d_in[9];
    const float* W_dec_mu = (const float*)d_in[10];
    const float* b_dec_mu = (const float*)d_in[11];
    const float* W_dec_lv = (const float*)d_in[12];
    const float* b_dec_lv = (const float*)d_in[13];
    float* out = (float*)d_out;

    bf16 *p_xb, *p_h, *p_z, *p_out4, *p_Wt1, *p_Wt2, *p_Wt3, *p_Wt4;
    float *p_kl, *p_row, *p_part, *p_b2, *p_b4;
    cudaGetSymbolAddress((void**)&p_xb, sc_xb);
    cudaGetSymbolAddress((void**)&p_h, sc_h);
    cudaGetSymbolAddress((void**)&p_z, sc_z);
    cudaGetSymbolAddress((void**)&p_out4, sc_out4);
    cudaGetSymbolAddress((void**)&p_kl, sc_kl);
    cudaGetSymbolAddress((void**)&p_row, sc_row);
    cudaGetSymbolAddress((void**)&p_part, sc_part);
    cudaGetSymbolAddress((void**)&p_Wt1, sc_Wt1);
    cudaGetSymbolAddress((void**)&p_Wt2, sc_Wt2);
    cudaGetSymbolAddress((void**)&p_Wt3, sc_Wt3);
    cudaGetSymbolAddress((void**)&p_Wt4, sc_Wt4);
    cudaGetSymbolAddress((void**)&p_b2, sc_b2);
    cudaGetSymbolAddress((void**)&p_b4, sc_b4);

    cudaFuncSetAttribute(gemm_mma<0>, cudaFuncAttributeMaxDynamicSharedMemorySize, SMEMSZ);
    cudaFuncSetAttribute(gemm_mma<1>, cudaFuncAttributeMaxDynamicSharedMemorySize, SMEMSZ);
    cudaFuncSetAttribute(gemm_mma<2>, cudaFuncAttributeMaxDynamicSharedMemorySize, SMEMSZ);

    // prep
    conv_x<<<(BATCH * DIN) / (256 * 8), 256>>>(x, p_xb);
    transpose_w<<<dim3(16, 32), dim3(32, 8)>>>(W_enc_h,  p_Wt1, 512, 1024, 512, 0);
    transpose_w<<<dim3(32, 2),  dim3(32, 8)>>>(W_enc_mu, p_Wt2, 1024, 64, 1024, 0);
    transpose_w<<<dim3(32, 2),  dim3(32, 8)>>>(W_enc_lv, p_Wt2, 1024, 64, 1024, 64);
    transpose_w<<<dim3(2, 32),  dim3(32, 8)>>>(W_dec_h,  p_Wt3, 64, 1024, 64, 0);
    transpose_w<<<dim3(32, 16), dim3(32, 8)>>>(W_dec_mu, p_Wt4, 1024, 512, 1024, 0);
    transpose_w<<<dim3(32, 16), dim3(32, 8)>>>(W_dec_lv, p_Wt4, 1024, 512, 1024, 512);
    concat_bias<<<1, 128>>>(b_enc_mu, b_enc_lv, p_b2, LAT);
    concat_bias<<<4, 256>>>(b_dec_mu, b_dec_lv, p_b4, DIN);

    // 1) h = tanh(x @ W1)
    gemm_mma<1><<<dim3(8, 512), 256, SMEMSZ>>>(p_xb, DIN, p_Wt1, b_enc_h, p_h, HID,
                                               nullptr, nullptr, nullptr);
    // 2) enc head -> z, kl
    gemm_mma<2><<<dim3(1, 512), 256, SMEMSZ>>>(p_h, HID, p_Wt2, p_b2, nullptr, 0,
                                               eps, p_z, p_kl);
    // 3) hd = tanh(z @ W3)
    gemm_mma<1><<<dim3(8, 512), 256, SMEMSZ>>>(p_z, LAT, p_Wt3, b_dec_h, p_h, HID,
                                               nullptr, nullptr, nullptr);
    // 4) logits|lvx = hd @ W4 (bf16 out)
    gemm_mma<0><<<dim3(8, 512), 256, SMEMSZ>>>(p_h, HID, p_Wt4, p_b4, p_out4, 2 * DIN,
                                               nullptr, nullptr, nullptr);
    // 5) per-row loss, 6) deterministic mean
    row_loss<<<BATCH, 256>>>(p_out4, x, p_kl, p_row);
    reduce_partial<<<256, 256>>>(p_row, p_part);
    reduce_final<<<1, 256>>>(p_part, out);
}

// round 14
// speedup vs baseline: 1.7929x; 1.0192x over previous
#include <cuda_runtime.h>
#include <cuda_bf16.h>
#include <cstdint>
#include <cstddef>

#define BATCH 65536
#define DIN   512
#define HID   1024
#define LAT   64
#define LOG2PI 1.8378770664093453f

typedef __nv_bfloat16 bf16;

// ---------------- scratch (__device__ globals; allocation-free rule) --------
__device__ bf16  sc_xb[(size_t)BATCH * DIN];        // x bf16             64MB
__device__ bf16  sc_h [(size_t)BATCH * HID];        // h / hd bf16       128MB
__device__ bf16  sc_z [(size_t)BATCH * LAT];        // z bf16              8MB
__device__ bf16  sc_out4[(size_t)BATCH * (2*DIN)];  // logits|lvx bf16   128MB
__device__ float sc_kl[BATCH];
__device__ float sc_row[BATCH];
__device__ float sc_part[256];
__device__ bf16  sc_Wt1[(size_t)HID * DIN];
__device__ bf16  sc_Wt2[(size_t)(2*LAT) * HID];
__device__ bf16  sc_Wt3[(size_t)HID * LAT];
__device__ bf16  sc_Wt4[(size_t)(2*DIN) * HID];
__device__ float sc_b2[2*LAT];
__device__ float sc_b4[2*DIN];

// ---------------- helpers ---------------------------------------------------
__device__ __forceinline__ uint32_t smem_u32(const void* p) {
    uint32_t a;
    asm("{ .reg .u64 t; cvta.to.shared.u64 t, %1; cvt.u32.u64 %0, t; }" : "=r"(a) : "l"(p));
    return a;
}
#define SWZ(off) ((off) ^ (((off) >> 3) & 0x70))

__device__ __forceinline__ void cp16(uint32_t dst, const void* src) {
    asm volatile("cp.async.cg.shared.global.L2::256B [%0], [%1], 16;" :: "r"(dst), "l"(src));
}
#define CP_COMMIT() asm volatile("cp.async.commit_group;" ::: "memory")
#define CP_WAIT(n)  asm volatile("cp.async.wait_group %0;" :: "n"(n) : "memory")

__device__ __forceinline__ void ldmX4(uint32_t& a0, uint32_t& a1, uint32_t& a2, uint32_t& a3,
                                      uint32_t addr) {
    asm volatile("ldmatrix.sync.aligned.m8n8.x4.shared.b16 {%0,%1,%2,%3}, [%4];"
                 : "=r"(a0), "=r"(a1), "=r"(a2), "=r"(a3) : "r"(addr));
}
__device__ __forceinline__ void mma16816(float& c0, float& c1, float& c2, float& c3,
                                         uint32_t a0, uint32_t a1, uint32_t a2, uint32_t a3,
                                         uint32_t b0, uint32_t b1) {
    asm volatile("mma.sync.aligned.m16n8k16.row.col.f32.bf16.bf16.f32 "
                 "{%0,%1,%2,%3}, {%4,%5,%6,%7}, {%8,%9}, {%0,%1,%2,%3};"
                 : "+f"(c0), "+f"(c1), "+f"(c2), "+f"(c3)
                 : "r"(a0), "r"(a1), "r"(a2), "r"(a3), "r"(b0), "r"(b1));
}

// ---------------- tile prefetch: 128 rows x 64 bf16, SW128, cp.async --------
__device__ __forceinline__ void prefetch_tile(const bf16* __restrict__ g, int pitch,
                                              int row0, int kofs, uint32_t sbase, int tid) {
#pragma unroll
    for (int u = 0; u < 4; u++) {
        int id  = tid + u * 256;
        int r   = id >> 3;
        int c16 = id & 7;
        uint32_t off = (uint32_t)(r * 128 + c16 * 16);
        cp16(sbase + SWZ(off), g + (size_t)(row0 + r) * pitch + kofs + c16 * 8);
    }
}

// ---------------- mma.sync GEMM: D = A[M,K] @ Bt[N,K]^T ---------------------
// block tile 128x128, BK=64, 256 threads (8 warps, 2x4), warp tile 64x32.
// 3-stage cp.async ring, ONE barrier per K-iteration, 2 CTAs/SM enforced.
// EPI: 0 = bias + bf16 store, 1 = bias+tanh+bf16 store, 2 = enc head (z, KL)
static constexpr int PAD = 130;
static constexpr int STAGE = 32768;
static constexpr int SMEMSZ = 3 * STAGE;

template<int EPI>
__global__ __launch_bounds__(256, 2) void gemm_mma(
    const bf16* __restrict__ A, int Ka,
    const bf16* __restrict__ Bt,
    const float* __restrict__ bias,
    void* __restrict__ Cout, int Np,
    const float* __restrict__ eps, bf16* __restrict__ zout, float* __restrict__ klout)
{
    extern __shared__ char smem[];
    const uint32_t sb = smem_u32(smem);
    const int tid = threadIdx.x, wid = tid >> 5, lane = tid & 31;
    const int wm = wid >> 2, wn = wid & 3;
    const int row0 = blockIdx.y * 128, col0 = blockIdx.x * 128;

    float c[4][4][4];
#pragma unroll
    for (int i = 0; i < 4; i++)
#pragma unroll
        for (int j = 0; j < 4; j++)
#pragma unroll
            for (int q = 0; q < 4; q++) c[i][j][q] = 0.0f;

    const int KT = Ka / 64;
    prefetch_tile(A,  Ka, row0, 0, sb, tid);
    prefetch_tile(Bt, Ka, col0, 0, sb + 16384, tid);
    CP_COMMIT();
    if (KT > 1) {
        prefetch_tile(A,  Ka, row0, 64, sb + STAGE, tid);
        prefetch_tile(Bt, Ka, col0, 64, sb + STAGE + 16384, tid);
    }
    CP_COMMIT();

    const int arow = wm * 64 + (lane & 15);
    const uint32_t acol = ((uint32_t)(lane >> 4)) << 4;
    // B x4 lane mapping: g = lane>>3 -> (n-subtile = g>>1, k-half = g&1)
    const int g = lane >> 3;
    const int bRowBase = wn * 32 + (g >> 1) * 8 + (lane & 7);
    const uint32_t bColHalf = (uint32_t)(g & 1) << 4;

    int stage = 0;
    for (int kt = 0; kt < KT; kt++) {
        CP_WAIT(1);
        __syncthreads();
        {
            int pf = kt + 2;
            int pstage = stage + 2; if (pstage >= 3) pstage -= 3;
            if (pf < KT) {
                prefetch_tile(A,  Ka, row0, pf * 64, sb + pstage * STAGE, tid);
                prefetch_tile(Bt, Ka, col0, pf * 64, sb + pstage * STAGE + 16384, tid);
            }
            CP_COMMIT();
        }
        const uint32_t SAb = sb + stage * STAGE;
        const uint32_t SBb = SAb + 16384;
#pragma unroll
        for (int ks = 0; ks < 4; ks++) {
            uint32_t af[4][4], bfr[4][2];
#pragma unroll
            for (int i = 0; i < 4; i++) {
                uint32_t off = (uint32_t)((arow + i * 16) * 128) + ks * 32 + acol;
                ldmX4(af[i][0], af[i][1], af[i][2], af[i][3], SAb + SWZ(off));
            }
#pragma unroll
            for (int jp = 0; jp < 2; jp++) {
                uint32_t off = (uint32_t)((bRowBase + jp * 16) * 128) + ks * 32 + bColHalf;
                ldmX4(bfr[jp*2][0], bfr[jp*2][1], bfr[jp*2+1][0], bfr[jp*2+1][1],
                      SBb + SWZ(off));
            }
#pragma unroll
            for (int i = 0; i < 4; i++)
#pragma unroll
                for (int j = 0; j < 4; j++)
                    mma16816(c[i][j][0], c[i][j][1], c[i][j][2], c[i][j][3],
                             af[i][0], af[i][1], af[i][2], af[i][3],
                             bfr[j][0], bfr[j][1]);
        }
        if (++stage == 3) stage = 0;
    }

    __syncthreads();
    float* stg = (float*)smem;
    {
        const int r0 = wm * 64 + (lane >> 2);
        const int cfix = wn * 32 + (lane & 3) * 2;
#pragma unroll
        for (int i = 0; i < 4; i++)
#pragma unroll
            for (int j = 0; j < 4; j++) {
                int sr = r0 + i * 16, scol = cfix + j * 8;
                stg[sr * PAD + scol]           = c[i][j][0];
                stg[sr * PAD + scol + 1]       = c[i][j][1];
                stg[(sr + 8) * PAD + scol]     = c[i][j][2];
                stg[(sr + 8) * PAD + scol + 1] = c[i][j][3];
            }
    }
    __syncthreads();

    if (EPI == 2) {
        if (tid < 128) {
            const int row = tid;
            const int r = row0 + row;
            float klacc = 0.0f;
            uint32_t zp[32];
            const float* er = eps + (size_t)r * LAT;
#pragma unroll
            for (int j = 0; j < 64; j += 2) {
                float mu0 = stg[row * PAD + j]     + bias[j];
                float mu1 = stg[row * PAD + j + 1] + bias[j + 1];
                float lv0 = stg[row * PAD + 64 + j]     + bias[64 + j];
                float lv1 = stg[row * PAD + 64 + j + 1] + bias[64 + j + 1];
                float z0 = fmaf(expf(0.5f * lv0), er[j],     mu0);
                float z1 = fmaf(expf(0.5f * lv1), er[j + 1], mu1);
                klacc += (1.0f + lv0 - mu0 * mu0 - expf(lv0));
                klacc += (1.0f + lv1 - mu1 * mu1 - expf(lv1));
                __nv_bfloat162 t = __floats2bfloat162_rn(z0, z1);
                zp[j >> 1] = *(uint32_t*)&t;
            }
            uint4* dst = (uint4*)(zout + (size_t)r * LAT);
#pragma unroll
            for (int q = 0; q < 8; q++) dst[q] = ((uint4*)zp)[q];
            klout[r] = -0.5f * klacc;
        }
    } else {
#pragma unroll
        for (int it = 0; it < 16; it++) {
            int id = tid + it * 256;
            int row = id >> 5, col = (id & 31) * 4;
            float v0 = stg[row * PAD + col]     + bias[col0 + col];
            float v1 = stg[row * PAD + col + 1] + bias[col0 + col + 1];
            float v2 = stg[row * PAD + col + 2] + bias[col0 + col + 2];
            float v3 = stg[row * PAD + col + 3] + bias[col0 + col + 3];
            if (EPI == 1) { v0 = tanhf(v0); v1 = tanhf(v1); v2 = tanhf(v2); v3 = tanhf(v3); }
            __nv_bfloat162 t0 = __floats2bfloat162_rn(v0, v1);
            __nv_bfloat162 t1 = __floats2bfloat162_rn(v2, v3);
            uint2 o = make_uint2(*(uint32_t*)&t0, *(uint32_t*)&t1);
            *(uint2*)((bf16*)Cout + (size_t)(row0 + row) * Np + col0 + col) = o;
        }
    }
}

// ---------------- GEMM3 dedicated: hd = tanh(z @ W3), K=64 ------------------
// One block = 128 rows, sweeps all 8 N-tiles of Wt3; A loaded ONCE.
// B in 3-stage ring; direct register->global tanh epilogue.
static constexpr int G3SMEM = 16384 + 3 * 16384;   // A + B ring = 64KB

__global__ __launch_bounds__(256, 2) void gemm3_mma(
    const bf16* __restrict__ A,        // z [B,64]
    const bf16* __restrict__ Bt,       // Wt3 [1024,64]
    const float* __restrict__ bias,    // b_dec_h [1024]
    bf16* __restrict__ Cout)           // hd [B,1024]
{
    extern __shared__ char smem[];
    const uint32_t sb = smem_u32(smem);
    const int tid = threadIdx.x, wid = tid >> 5, lane = tid & 31;
    const int wm = wid >> 2, wn = wid & 3;
    const int row0 = blockIdx.x * 128;

    prefetch_tile(A,  LAT, row0, 0, sb, tid);
    prefetch_tile(Bt, LAT, 0,    0, sb + 16384, tid);
    CP_COMMIT();
    prefetch_tile(Bt, LAT, 128,  0, sb + 16384 + 16384, tid);
    CP_COMMIT();

    const int arow = wm * 64 + (lane & 15);
    const uint32_t acol = ((uint32_t)(lane >> 4)) << 4;
    const int g = lane >> 3;
    const int bRowBase = wn * 32 + (g >> 1) * 8 + (lane & 7);
    const uint32_t bColHalf = (uint32_t)(g & 1) << 4;
    const int fr0 = wm * 64 + (lane >> 2);
    const int fc0 = wn * 32 + (lane & 3) * 2;

    for (int nt = 0; nt < 8; nt++) {
        CP_WAIT(1);
        __syncthreads();
        {
            int pf = nt + 2;
            int slot = pf % 3;
            if (pf < 8) prefetch_tile(Bt, LAT, pf * 128, 0, sb + 16384 + slot * 16384, tid);
            CP_COMMIT();
        }
        const uint32_t SBb = sb + 16384 + (nt % 3) * 16384;
        float c[4][4][4];
#pragma unroll
        for (int i = 0; i < 4; i++)
#pragma unroll
            for (int j = 0; j < 4; j++)
#pragma unroll
                for (int q = 0; q < 4; q++) c[i][j][q] = 0.0f;
#pragma unroll
        for (int ks = 0; ks < 4; ks++) {
            uint32_t af[4][4], bfr[4][2];
#pragma unroll
            for (int i = 0; i < 4; i++) {
                uint32_t off = (uint32_t)((arow + i * 16) * 128) + ks * 32 + acol;
                ldmX4(af[i][0], af[i][1], af[i][2], af[i][3], sb + SWZ(off));
            }
#pragma unroll
            for (int jp = 0; jp < 2; jp++) {
                uint32_t off = (uint32_t)((bRowBase + jp * 16) * 128) + ks * 32 + bColHalf;
                ldmX4(bfr[jp*2][0], bfr[jp*2][1], bfr[jp*2+1][0], bfr[jp*2+1][1],
                      SBb + SWZ(off));
            }
#pragma unroll
            for (int i = 0; i < 4; i++)
#pragma unroll
                for (int j = 0; j < 4; j++)
                    mma16816(c[i][j][0], c[i][j][1], c[i][j][2], c[i][j][3],
                             af[i][0], af[i][1], af[i][2], af[i][3],
                             bfr[j][0], bfr[j][1]);
        }
        // direct epilogue: bias + tanh + bf16x2 stores
        const int col0 = nt * 128;
#pragma unroll
        for (int i = 0; i < 4; i++)
#pragma unroll
            for (int j = 0; j < 4; j++) {
                int sc = col0 + fc0 + j * 8;
                float b0 = bias[sc], b1 = bias[sc + 1];
                int r = row0 + fr0 + i * 16;
                __nv_bfloat162 t0 = __floats2bfloat162_rn(tanhf(c[i][j][0] + b0),
                                                          tanhf(c[i][j][1] + b1));
                __nv_bfloat162 t1 = __floats2bfloat162_rn(tanhf(c[i][j][2] + b0),
                                                          tanhf(c[i][j][3] + b1));
                *(uint32_t*)(Cout + (size_t)r * HID + sc)       = *(uint32_t*)&t0;
                *(uint32_t*)(Cout + (size_t)(r + 8) * HID + sc) = *(uint32_t*)&t1;
            }
    }
}

// ---------------- weight transpose+convert ----------------------------------
__global__ void transpose_w(const float* __restrict__ src, bf16* __restrict__ dst,
                            int Ks, int Ns, int Kd, int n_off) {
    __shared__ float tile[32][33];
    int k0 = blockIdx.x * 32, n0 = blockIdx.y * 32;
    for (int i = threadIdx.y; i < 32; i += 8)
        tile[i][threadIdx.x] = src[(size_t)(k0 + i) * Ns + n0 + threadIdx.x];
    __syncthreads();
    for (int i = threadIdx.y; i < 32; i += 8)
        dst[(size_t)(n_off + n0 + i) * Kd + k0 + threadIdx.x] =
            __float2bfloat16(tile[threadIdx.x][i]);
}

__global__ void concat_bias(const float* __restrict__ a, const float* __restrict__ b,
                            float* __restrict__ d, int n) {
    int i = blockIdx.x * blockDim.x + threadIdx.x;
    if (i < n) d[i] = a[i];
    else if (i < 2 * n) d[i] = b[i - n];
}

__global__ void conv_x(const float* __restrict__ x, bf16* __restrict__ xb) {
    size_t i = ((size_t)blockIdx.x * blockDim.x + threadIdx.x) * 8;
    float4 a = *(const float4*)(x + i);
    float4 b = *(const float4*)(x + i + 4);
    uint32_t p[4];
    __nv_bfloat162 t;
    t = __floats2bfloat162_rn(a.x, a.y); p[0] = *(uint32_t*)&t;
    t = __floats2bfloat162_rn(a.z, a.w); p[1] = *(uint32_t*)&t;
    t = __floats2bfloat162_rn(b.x, b.y); p[2] = *(uint32_t*)&t;
    t = __floats2bfloat162_rn(b.z, b.w); p[3] = *(uint32_t*)&t;
    *(uint4*)(xb + i) = *(uint4*)p;
}

// ---------------- per-row softmax + likelihood (bf16 logits/lvx) ------------
__global__ void row_loss(const bf16* __restrict__ out4, const float* __restrict__ x,
                         const float* __restrict__ kl, float* __restrict__ rowout) {
    const int row = blockIdx.x;
    const int t = threadIdx.x;
    __shared__ float sh[8];
    const bf16* lr = out4 + (size_t)row * (2 * DIN);
    const bf16* vr = lr + DIN;
    float l0 = __bfloat162float(lr[t]), l1 = __bfloat162float(lr[t + 256]);

    float m = fmaxf(l0, l1);
#pragma unroll
    for (int o = 16; o > 0; o >>= 1) m = fmaxf(m, __shfl_xor_sync(0xffffffffu, m, o));
    if ((t & 31) == 0) sh[t >> 5] = m;
    __syncthreads();
    m = sh[0];
#pragma unroll
    for (int w = 1; w < 8; w++) m = fmaxf(m, sh[w]);
    __syncthreads();

    float e0 = expf(l0 - m), e1 = expf(l1 - m);
    float s = e0 + e1;
#pragma unroll
    for (int o = 16; o > 0; o >>= 1) s += __shfl_xor_sync(0xffffffffu, s, o);
    if ((t & 31) == 0) sh[t >> 5] = s;
    __syncthreads();
    s = 0.0f;
#pragma unroll
    for (int w = 0; w < 8; w++) s += sh[w];
    __syncthreads();
    float inv = 1.0f / s;

    const float* xr = x + (size_t)row * DIN;
    float acc = 0.0f;
    {
        float p = e0 * inv, xv = xr[t];
        float lv = __bfloat162float(vr[t]);
        float d = xv - p;
        acc += lv + d * d * expf(-lv);
        p = e1 * inv; xv = xr[t + 256];
        lv = __bfloat162float(vr[t + 256]);
        d = xv - p;
        acc += lv + d * d * expf(-lv);
    }
#pragma unroll
    for (int o = 16; o > 0; o >>= 1) acc += __shfl_xor_sync(0xffffffffu, acc, o);
    if ((t & 31) == 0) sh[t >> 5] = acc;
    __syncthreads();
    if (t == 0) {
        float tot = 0.0f;
#pragma unroll
        for (int w = 0; w < 8; w++) tot += sh[w];
        float ln_pxz = -0.5f * (tot + (float)DIN * LOG2PI);
        rowout[row] = ln_pxz - kl[row];
    }
}

// ---------------- deterministic mean ----------------------------------------
__global__ void reduce_partial(const float* __restrict__ in, float* __restrict__ part) {
    const int t = threadIdx.x;
    __shared__ float sh[8];
    float v = in[blockIdx.x * 256 + t];
#pragma unroll
    for (int o = 16; o > 0; o >>= 1) v += __shfl_xor_sync(0xffffffffu, v, o);
    if ((t & 31) == 0) sh[t >> 5] = v;
    __syncthreads();
    if (t == 0) {
        float s = 0.0f;
#pragma unroll
        for (int w = 0; w < 8; w++) s += sh[w];
        part[blockIdx.x] = s;
    }
}
__global__ void reduce_final(const float* __restrict__ part, float* __restrict__ out) {
    const int t = threadIdx.x;
    __shared__ float sh[8];
    float v = part[t];
#pragma unroll
    for (int o = 16; o > 0; o >>= 1) v += __shfl_xor_sync(0xffffffffu, v, o);
    if ((t & 31) == 0) sh[t >> 5] = v;
    __syncthreads();
    if (t == 0) {
        float s = 0.0f;
#pragma unroll
        for (int w = 0; w < 8; w++) s += sh[w];
        out[0] = s * (1.0f / (float)BATCH);
    }
}

// ---------------- launch ----------------------------------------------------
extern "C" void kernel_launch(void* const* d_in, const int* in_sizes, int n_in,
                              void* d_out, int out_size) {
    const float* x        = (const float*)d_in[0];
    const float* eps      = (const float*)d_in[1];
    const float* W_enc_h  = (const float*)d_in[2];
    const float* b_enc_h  = (const float*)d_in[3];
    const float* W_enc_mu = (const float*)d_in[4];
    const float* b_enc_mu = (const float*)d_in[5];
    const float* W_enc_lv = (const float*)d_in[6];
    const float* b_enc_lv = (const float*)d_in[7];
    const float* W_dec_h  = (const float*)d_in[8];
    const float* b_dec_h  = (const float*)d_in[9];
    const float* W_dec_mu = (const float*)d_in[10];
    const float* b_dec_mu = (const float*)d_in[11];
    const float* W_dec_lv = (const float*)d_in[12];
    const float* b_dec_lv = (const float*)d_in[13];
    float* out = (float*)d_out;

    bf16 *p_xb, *p_h, *p_z, *p_out4, *p_Wt1, *p_Wt2, *p_Wt3, *p_Wt4;
    float *p_kl, *p_row, *p_part, *p_b2, *p_b4;
    cudaGetSymbolAddress((void**)&p_xb, sc_xb);
    cudaGetSymbolAddress((void**)&p_h, sc_h);
    cudaGetSymbolAddress((void**)&p_z, sc_z);
    cudaGetSymbolAddress((void**)&p_out4, sc_out4);
    cudaGetSymbolAddress((void**)&p_kl, sc_kl);
    cudaGetSymbolAddress((void**)&p_row, sc_row);
    cudaGetSymbolAddress((void**)&p_part, sc_part);
    cudaGetSymbolAddress((void**)&p_Wt1, sc_Wt1);
    cudaGetSymbolAddress((void**)&p_Wt2, sc_Wt2);
    cudaGetSymbolAddress((void**)&p_Wt3, sc_Wt3);
    cudaGetSymbolAddress((void**)&p_Wt4, sc_Wt4);
    cudaGetSymbolAddress((void**)&p_b2, sc_b2);
    cudaGetSymbolAddress((void**)&p_b4, sc_b4);

    cudaFuncSetAttribute(gemm_mma<0>, cudaFuncAttributeMaxDynamicSharedMemorySize, SMEMSZ);
    cudaFuncSetAttribute(gemm_mma<1>, cudaFuncAttributeMaxDynamicSharedMemorySize, SMEMSZ);
    cudaFuncSetAttribute(gemm_mma<2>, cudaFuncAttributeMaxDynamicSharedMemorySize, SMEMSZ);
    cudaFuncSetAttribute(gemm3_mma,   cudaFuncAttributeMaxDynamicSharedMemorySize, G3SMEM);

    // prep
    conv_x<<<(BATCH * DIN) / (256 * 8), 256>>>(x, p_xb);
    transpose_w<<<dim3(16, 32), dim3(32, 8)>>>(W_enc_h,  p_Wt1, 512, 1024, 512, 0);
    transpose_w<<<dim3(32, 2),  dim3(32, 8)>>>(W_enc_mu, p_Wt2, 1024, 64, 1024, 0);
    transpose_w<<<dim3(32, 2),  dim3(32, 8)>>>(W_enc_lv, p_Wt2, 1024, 64, 1024, 64);
    transpose_w<<<dim3(2, 32),  dim3(32, 8)>>>(W_dec_h,  p_Wt3, 64, 1024, 64, 0);
    transpose_w<<<dim3(32, 16), dim3(32, 8)>>>(W_dec_mu, p_Wt4, 1024, 512, 1024, 0);
    transpose_w<<<dim3(32, 16), dim3(32, 8)>>>(W_dec_lv, p_Wt4, 1024, 512, 1024, 512);
    concat_bias<<<1, 128>>>(b_enc_mu, b_enc_lv, p_b2, LAT);
    concat_bias<<<4, 256>>>(b_dec_mu, b_dec_lv, p_b4, DIN);

    // 1) h = tanh(x @ W1)
    gemm_mma<1><<<dim3(8, 512), 256, SMEMSZ>>>(p_xb, DIN, p_Wt1, b_enc_h, p_h, HID,
                                               nullptr, nullptr, nullptr);
    // 2) enc head -> z, kl
    gemm_mma<2><<<dim3(1, 512), 256, SMEMSZ>>>(p_h, HID, p_Wt2, p_b2, nullptr, 0,
                                               eps, p_z, p_kl);
    // 3) hd = tanh(z @ W3)  (dedicated K=64 kernel, A reused across 8 N-tiles)
    gemm3_mma<<<BATCH / 128, 256, G3SMEM>>>(p_z, p_Wt3, b_dec_h, p_h);
    // 4) logits|lvx = hd @ W4 (bf16 out)
    gemm_mma<0><<<dim3(8, 512), 256, SMEMSZ>>>(p_h, HID, p_Wt4, p_b4, p_out4, 2 * DIN,
                                               nullptr, nullptr, nullptr);
    // 5) per-row loss, 6) deterministic mean
    row_loss<<<BATCH, 256>>>(p_out4, x, p_kl, p_row);
    reduce_partial<<<256, 256>>>(p_row, p_part);
    reduce_final<<<1, 256>>>(p_part, out);
}

// round 16
// speedup vs baseline: 1.8227x; 1.0167x over previous
#include <cuda_runtime.h>
#include <cuda_bf16.h>
#include <cstdint>
#include <cstddef>

#define BATCH 65536
#define DIN   512
#define HID   1024
#define LAT   64
#define LOG2PI 1.8378770664093453f

typedef __nv_bfloat16 bf16;

// ---------------- scratch (__device__ globals; allocation-free rule) --------
__device__ bf16  sc_xb[(size_t)BATCH * DIN];        // x bf16             64MB
__device__ bf16  sc_h [(size_t)BATCH * HID];        // h / hd bf16       128MB
__device__ bf16  sc_out4[(size_t)BATCH * (2*DIN)];  // logits|lvx bf16   128MB
__device__ float sc_kl[BATCH];
__device__ float sc_row[BATCH];
__device__ float sc_part[256];
__device__ bf16  sc_Wt1[(size_t)HID * DIN];
__device__ bf16  sc_Wt2[(size_t)(2*LAT) * HID];
__device__ bf16  sc_Wt3[(size_t)HID * LAT];
__device__ bf16  sc_Wt4[(size_t)(2*DIN) * HID];
__device__ float sc_b2[2*LAT];
__device__ float sc_b4[2*DIN];

// ---------------- helpers ---------------------------------------------------
__device__ __forceinline__ uint32_t smem_u32(const void* p) {
    uint32_t a;
    asm("{ .reg .u64 t; cvta.to.shared.u64 t, %1; cvt.u32.u64 %0, t; }" : "=r"(a) : "l"(p));
    return a;
}
#define SWZ(off) ((off) ^ (((off) >> 3) & 0x70))

__device__ __forceinline__ void cp16(uint32_t dst, const void* src) {
    asm volatile("cp.async.cg.shared.global.L2::256B [%0], [%1], 16;" :: "r"(dst), "l"(src));
}
#define CP_COMMIT() asm volatile("cp.async.commit_group;" ::: "memory")
#define CP_WAIT(n)  asm volatile("cp.async.wait_group %0;" :: "n"(n) : "memory")

__device__ __forceinline__ void ldmX4(uint32_t& a0, uint32_t& a1, uint32_t& a2, uint32_t& a3,
                                      uint32_t addr) {
    asm volatile("ldmatrix.sync.aligned.m8n8.x4.shared.b16 {%0,%1,%2,%3}, [%4];"
                 : "=r"(a0), "=r"(a1), "=r"(a2), "=r"(a3) : "r"(addr));
}
__device__ __forceinline__ void mma16816(float& c0, float& c1, float& c2, float& c3,
                                         uint32_t a0, uint32_t a1, uint32_t a2, uint32_t a3,
                                         uint32_t b0, uint32_t b1) {
    asm volatile("mma.sync.aligned.m16n8k16.row.col.f32.bf16.bf16.f32 "
                 "{%0,%1,%2,%3}, {%4,%5,%6,%7}, {%8,%9}, {%0,%1,%2,%3};"
                 : "+f"(c0), "+f"(c1), "+f"(c2), "+f"(c3)
                 : "r"(a0), "r"(a1), "r"(a2), "r"(a3), "r"(b0), "r"(b1));
}

// ---------------- tile prefetch: 128 rows x 64 bf16, SW128, cp.async --------
__device__ __forceinline__ void prefetch_tile(const bf16* __restrict__ g, int pitch,
                                              int row0, int kofs, uint32_t sbase, int tid) {
#pragma unroll
    for (int u = 0; u < 4; u++) {
        int id  = tid + u * 256;
        int r   = id >> 3;
        int c16 = id & 7;
        uint32_t off = (uint32_t)(r * 128 + c16 * 16);
        cp16(sbase + SWZ(off), g + (size_t)(row0 + r) * pitch + kofs + c16 * 8);
    }
}

// ---------------- mma.sync GEMM: D = A[M,K] @ Bt[N,K]^T ---------------------
// block tile 128x128, BK=64, 256 threads (8 warps, 2x4), warp tile 64x32.
// 3-stage cp.async ring, ONE barrier per K-iteration, 2 CTAs/SM enforced.
// EPI: 0 = bias + bf16 store, 1 = bias+tanh+bf16 store
static constexpr int PAD = 130;
static constexpr int STAGE = 32768;
static constexpr int SMEMSZ = 3 * STAGE;

template<int EPI>
__global__ __launch_bounds__(256, 2) void gemm_mma(
    const bf16* __restrict__ A, int Ka,
    const bf16* __restrict__ Bt,
    const float* __restrict__ bias,
    bf16* __restrict__ Cout, int Np)
{
    extern __shared__ char smem[];
    const uint32_t sb = smem_u32(smem);
    const int tid = threadIdx.x, wid = tid >> 5, lane = tid & 31;
    const int wm = wid >> 2, wn = wid & 3;
    const int row0 = blockIdx.y * 128, col0 = blockIdx.x * 128;

    float c[4][4][4];
#pragma unroll
    for (int i = 0; i < 4; i++)
#pragma unroll
        for (int j = 0; j < 4; j++)
#pragma unroll
            for (int q = 0; q < 4; q++) c[i][j][q] = 0.0f;

    const int KT = Ka / 64;
    prefetch_tile(A,  Ka, row0, 0, sb, tid);
    prefetch_tile(Bt, Ka, col0, 0, sb + 16384, tid);
    CP_COMMIT();
    if (KT > 1) {
        prefetch_tile(A,  Ka, row0, 64, sb + STAGE, tid);
        prefetch_tile(Bt, Ka, col0, 64, sb + STAGE + 16384, tid);
    }
    CP_COMMIT();

    const int arow = wm * 64 + (lane & 15);
    const uint32_t acol = ((uint32_t)(lane >> 4)) << 4;
    const int g = lane >> 3;
    const int bRowBase = wn * 32 + (g >> 1) * 8 + (lane & 7);
    const uint32_t bColHalf = (uint32_t)(g & 1) << 4;

    int stage = 0;
    for (int kt = 0; kt < KT; kt++) {
        CP_WAIT(1);
        __syncthreads();
        {
            int pf = kt + 2;
            int pstage = stage + 2; if (pstage >= 3) pstage -= 3;
            if (pf < KT) {
                prefetch_tile(A,  Ka, row0, pf * 64, sb + pstage * STAGE, tid);
                prefetch_tile(Bt, Ka, col0, pf * 64, sb + pstage * STAGE + 16384, tid);
            }
            CP_COMMIT();
        }
        const uint32_t SAb = sb + stage * STAGE;
        const uint32_t SBb = SAb + 16384;
#pragma unroll
        for (int ks = 0; ks < 4; ks++) {
            uint32_t af[4][4], bfr[4][2];
#pragma unroll
            for (int i = 0; i < 4; i++) {
                uint32_t off = (uint32_t)((arow + i * 16) * 128) + ks * 32 + acol;
                ldmX4(af[i][0], af[i][1], af[i][2], af[i][3], SAb + SWZ(off));
            }
#pragma unroll
            for (int jp = 0; jp < 2; jp++) {
                uint32_t off = (uint32_t)((bRowBase + jp * 16) * 128) + ks * 32 + bColHalf;
                ldmX4(bfr[jp*2][0], bfr[jp*2][1], bfr[jp*2+1][0], bfr[jp*2+1][1],
                      SBb + SWZ(off));
            }
#pragma unroll
            for (int i = 0; i < 4; i++)
#pragma unroll
                for (int j = 0; j < 4; j++)
                    mma16816(c[i][j][0], c[i][j][1], c[i][j][2], c[i][j][3],
                             af[i][0], af[i][1], af[i][2], af[i][3],
                             bfr[j][0], bfr[j][1]);
        }
        if (++stage == 3) stage = 0;
    }

    __syncthreads();
    float* stg = (float*)smem;
    {
        const int r0 = wm * 64 + (lane >> 2);
        const int cfix = wn * 32 + (lane & 3) * 2;
#pragma unroll
        for (int i = 0; i < 4; i++)
#pragma unroll
            for (int j = 0; j < 4; j++) {
                int sr = r0 + i * 16, scol = cfix + j * 8;
                stg[sr * PAD + scol]           = c[i][j][0];
                stg[sr * PAD + scol + 1]       = c[i][j][1];
                stg[(sr + 8) * PAD + scol]     = c[i][j][2];
                stg[(sr + 8) * PAD + scol + 1] = c[i][j][3];
            }
    }
    __syncthreads();

#pragma unroll
    for (int it = 0; it < 16; it++) {
        int id = tid + it * 256;
        int row = id >> 5, col = (id & 31) * 4;
        float v0 = stg[row * PAD + col]     + bias[col0 + col];
        float v1 = stg[row * PAD + col + 1] + bias[col0 + col + 1];
        float v2 = stg[row * PAD + col + 2] + bias[col0 + col + 2];
        float v3 = stg[row * PAD + col + 3] + bias[col0 + col + 3];
        if (EPI == 1) { v0 = tanhf(v0); v1 = tanhf(v1); v2 = tanhf(v2); v3 = tanhf(v3); }
        __nv_bfloat162 t0 = __floats2bfloat162_rn(v0, v1);
        __nv_bfloat162 t1 = __floats2bfloat162_rn(v2, v3);
        uint2 o = make_uint2(*(uint32_t*)&t0, *(uint32_t*)&t1);
        *(uint2*)(Cout + (size_t)(row0 + row) * Np + col0 + col) = o;
    }
}

// ---------------- enc23: GEMM2 (enc head) + GEMM3 fused ---------------------
// Phase 1: (mu|lv) = h @ Wt2^T (K=1024, N=128); epilogue -> z (smem bf16), KL.
// Phase 3: hd = tanh(z @ Wt3^T) (K=64, 8 N-tiles), z read from smem.
static constexpr int ZOFF = 81920;                 // z tile: 128 x 64 bf16 = 16KB

__global__ __launch_bounds__(256, 2) void enc23(
    const bf16* __restrict__ A,        // h [B,1024]
    const bf16* __restrict__ Bt2,      // Wt2 [128,1024]
    const float* __restrict__ b2,      // [128]
    const float* __restrict__ eps,     // [B,64] fp32
    float* __restrict__ klout,         // [B]
    const bf16* __restrict__ Bt3,      // Wt3 [1024,64]
    const float* __restrict__ b3,      // [1024]
    bf16* __restrict__ Cout)           // hd [B,1024]
{
    extern __shared__ char smem[];
    const uint32_t sb = smem_u32(smem);
    const int tid = threadIdx.x, wid = tid >> 5, lane = tid & 31;
    const int wm = wid >> 2, wn = wid & 3;
    const int row0 = blockIdx.x * 128;

    const int arow = wm * 64 + (lane & 15);
    const uint32_t acol = ((uint32_t)(lane >> 4)) << 4;
    const int g = lane >> 3;
    const int bRowBase = wn * 32 + (g >> 1) * 8 + (lane & 7);
    const uint32_t bColHalf = (uint32_t)(g & 1) << 4;

    // ================= phase 1: GEMM2 =================
    {
        float c[4][4][4];
#pragma unroll
        for (int i = 0; i < 4; i++)
#pragma unroll
            for (int j = 0; j < 4; j++)
#pragma unroll
                for (int q = 0; q < 4; q++) c[i][j][q] = 0.0f;

        prefetch_tile(A,   HID, row0, 0, sb, tid);
        prefetch_tile(Bt2, HID, 0,    0, sb + 16384, tid);
        CP_COMMIT();
        prefetch_tile(A,   HID, row0, 64, sb + STAGE, tid);
        prefetch_tile(Bt2, HID, 0,    64, sb + STAGE + 16384, tid);
        CP_COMMIT();

        int stage = 0;
        for (int kt = 0; kt < 16; kt++) {
            CP_WAIT(1);
            __syncthreads();
            {
                int pf = kt + 2;
                int pstage = stage + 2; if (pstage >= 3) pstage -= 3;
                if (pf < 16) {
                    prefetch_tile(A,   HID, row0, pf * 64, sb + pstage * STAGE, tid);
                    prefetch_tile(Bt2, HID, 0,    pf * 64, sb + pstage * STAGE + 16384, tid);
                }
                CP_COMMIT();
            }
            const uint32_t SAb = sb + stage * STAGE;
            const uint32_t SBb = SAb + 16384;
#pragma unroll
            for (int ks = 0; ks < 4; ks++) {
                uint32_t af[4][4], bfr[4][2];
#pragma unroll
                for (int i = 0; i < 4; i++) {
                    uint32_t off = (uint32_t)((arow + i * 16) * 128) + ks * 32 + acol;
                    ldmX4(af[i][0], af[i][1], af[i][2], af[i][3], SAb + SWZ(off));
                }
#pragma unroll
                for (int jp = 0; jp < 2; jp++) {
                    uint32_t off = (uint32_t)((bRowBase + jp * 16) * 128) + ks * 32 + bColHalf;
                    ldmX4(bfr[jp*2][0], bfr[jp*2][1], bfr[jp*2+1][0], bfr[jp*2+1][1],
                          SBb + SWZ(off));
                }
#pragma unroll
                for (int i = 0; i < 4; i++)
#pragma unroll
                    for (int j = 0; j < 4; j++)
                        mma16816(c[i][j][0], c[i][j][1], c[i][j][2], c[i][j][3],
                                 af[i][0], af[i][1], af[i][2], af[i][3],
                                 bfr[j][0], bfr[j][1]);
            }
            if (++stage == 3) stage = 0;
        }

        __syncthreads();
        float* stg = (float*)smem;
        {
            const int r0 = wm * 64 + (lane >> 2);
            const int cfix = wn * 32 + (lane & 3) * 2;
#pragma unroll
            for (int i = 0; i < 4; i++)
#pragma unroll
                for (int j = 0; j < 4; j++) {
                    int sr = r0 + i * 16, scol = cfix + j * 8;
                    stg[sr * PAD + scol]           = c[i][j][0];
                    stg[sr * PAD + scol + 1]       = c[i][j][1];
                    stg[(sr + 8) * PAD + scol]     = c[i][j][2];
                    stg[(sr + 8) * PAD + scol + 1] = c[i][j][3];
                }
        }
        __syncthreads();

        // epilogue: mu/lv -> z (smem bf16 SW128 @ ZOFF), KL
        if (tid < 128) {
            const int row = tid;
            const int r = row0 + row;
            float klacc = 0.0f;
            uint32_t zp[32];
            const float* er = eps + (size_t)r * LAT;
#pragma unroll
            for (int j = 0; j < 64; j += 2) {
                float mu0 = stg[row * PAD + j]     + b2[j];
                float mu1 = stg[row * PAD + j + 1] + b2[j + 1];
                float lv0 = stg[row * PAD + 64 + j]     + b2[64 + j];
                float lv1 = stg[row * PAD + 64 + j + 1] + b2[64 + j + 1];
                float z0 = fmaf(expf(0.5f * lv0), er[j],     mu0);
                float z1 = fmaf(expf(0.5f * lv1), er[j + 1], mu1);
                klacc += (1.0f + lv0 - mu0 * mu0 - expf(lv0));
                klacc += (1.0f + lv1 - mu1 * mu1 - expf(lv1));
                __nv_bfloat162 t = __floats2bfloat162_rn(z0, z1);
                zp[j >> 1] = *(uint32_t*)&t;
            }
#pragma unroll
            for (int q = 0; q < 8; q++) {
                uint32_t off = (uint32_t)(row * 128 + q * 16);
                *(uint4*)(smem + ZOFF + SWZ(off)) = ((uint4*)zp)[q];
            }
            klout[r] = -0.5f * klacc;
        }
        __syncthreads();
    }

    // ================= phase 3: GEMM3 (A = z in smem) =================
    {
        const uint32_t SAz = sb + ZOFF;
        prefetch_tile(Bt3, LAT, 0,   0, sb, tid);
        CP_COMMIT();
        prefetch_tile(Bt3, LAT, 128, 0, sb + 16384, tid);
        CP_COMMIT();

        const int fr0 = wm * 64 + (lane >> 2);
        const int fc0 = wn * 32 + (lane & 3) * 2;

        for (int nt = 0; nt < 8; nt++) {
            CP_WAIT(1);
            __syncthreads();
            {
                int pf = nt + 2;
                int slot = pf % 3;
                if (pf < 8) prefetch_tile(Bt3, LAT, pf * 128, 0, sb + slot * 16384, tid);
                CP_COMMIT();
            }
            const uint32_t SBb = sb + (nt % 3) * 16384;
            float c[4][4][4];
#pragma unroll
            for (int i = 0; i < 4; i++)
#pragma unroll
                for (int j = 0; j < 4; j++)
#pragma unroll
                    for (int q = 0; q < 4; q++) c[i][j][q] = 0.0f;
#pragma unroll
            for (int ks = 0; ks < 4; ks++) {
                uint32_t af[4][4], bfr[4][2];
#pragma unroll
                for (int i = 0; i < 4; i++) {
                    uint32_t off = (uint32_t)((arow + i * 16) * 128) + ks * 32 + acol;
                    ldmX4(af[i][0], af[i][1], af[i][2], af[i][3], SAz + SWZ(off));
                }
#pragma unroll
                for (int jp = 0; jp < 2; jp++) {
                    uint32_t off = (uint32_t)((bRowBase + jp * 16) * 128) + ks * 32 + bColHalf;
                    ldmX4(bfr[jp*2][0], bfr[jp*2][1], bfr[jp*2+1][0], bfr[jp*2+1][1],
                          SBb + SWZ(off));
                }
#pragma unroll
                for (int i = 0; i < 4; i++)
#pragma unroll
                    for (int j = 0; j < 4; j++)
                        mma16816(c[i][j][0], c[i][j][1], c[i][j][2], c[i][j][3],
                                 af[i][0], af[i][1], af[i][2], af[i][3],
                                 bfr[j][0], bfr[j][1]);
            }
            const int col0 = nt * 128;
#pragma unroll
            for (int i = 0; i < 4; i++)
#pragma unroll
                for (int j = 0; j < 4; j++) {
                    int sc = col0 + fc0 + j * 8;
                    float b0 = b3[sc], b1 = b3[sc + 1];
                    int r = row0 + fr0 + i * 16;
                    __nv_bfloat162 t0 = __floats2bfloat162_rn(tanhf(c[i][j][0] + b0),
                                                              tanhf(c[i][j][1] + b1));
                    __nv_bfloat162 t1 = __floats2bfloat162_rn(tanhf(c[i][j][2] + b0),
                                                              tanhf(c[i][j][3] + b1));
                    *(uint32_t*)(Cout + (size_t)r * HID + sc)       = *(uint32_t*)&t0;
                    *(uint32_t*)(Cout + (size_t)(r + 8) * HID + sc) = *(uint32_t*)&t1;
                }
        }
    }
}

// ---------------- fused prep: all weight transposes + biases ----------------
// grid: 1729 blocks of 256 (32x8). Regions:
//  [0,512)    W_enc_h  [512,1024]  -> Wt1 (Kd=512,  n_off=0)    kx=16, ny=32
//  [512,576)  W_enc_mu [1024,64]   -> Wt2 (Kd=1024, n_off=0)    kx=32, ny=2
//  [576,640)  W_enc_lv [1024,64]   -> Wt2 (Kd=1024, n_off=64)   kx=32, ny=2
//  [640,704)  W_dec_h  [64,1024]   -> Wt3 (Kd=64,   n_off=0)    kx=2,  ny=32
//  [704,1216) W_dec_mu [1024,512]  -> Wt4 (Kd=1024, n_off=0)    kx=32, ny=16
//  [1216,1728)W_dec_lv [1024,512]  -> Wt4 (Kd=1024, n_off=512)  kx=32, ny=16
//  1728       biases
__global__ void prep_weights(
    const float* __restrict__ W1s, const float* __restrict__ W2ms,
    const float* __restrict__ W2ls, const float* __restrict__ W3s,
    const float* __restrict__ W4ms, const float* __restrict__ W4ls,
    bf16* __restrict__ Wt1, bf16* __restrict__ Wt2,
    bf16* __restrict__ Wt3, bf16* __restrict__ Wt4,
    const float* __restrict__ bemu, const float* __restrict__ belv,
    const float* __restrict__ bdmu, const float* __restrict__ bdlv,
    float* __restrict__ pb2, float* __restrict__ pb4)
{
    const int b = blockIdx.x;
    const int tx = threadIdx.x, ty = threadIdx.y;
    if (b == 1728) {
        int tid = ty * 32 + tx;
        if (tid < 64) pb2[tid] = bemu[tid];
        else if (tid < 128) pb2[tid] = belv[tid - 64];
        for (int i = tid; i < 512; i += 256) {
            pb4[i] = bdmu[i];
            pb4[512 + i] = bdlv[i];
        }
        return;
    }
    const float* src; bf16* dst; int Ns, Kd, n_off, KX, t;
    if (b < 512)       { src = W1s;  dst = Wt1; Ns = 1024; Kd = 512;  n_off = 0;   KX = 16; t = b; }
    else if (b < 576)  { src = W2ms; dst = Wt2; Ns = 64;   Kd = 1024; n_off = 0;   KX = 32; t = b - 512; }
    else if (b < 640)  { src = W2ls; dst = Wt2; Ns = 64;   Kd = 1024; n_off = 64;  KX = 32; t = b - 576; }
    else if (b < 704)  { src = W3s;  dst = Wt3; Ns = 1024; Kd = 64;   n_off = 0;   KX = 2;  t = b - 640; }
    else if (b < 1216) { src = W4ms; dst = Wt4; Ns = 512;  Kd = 1024; n_off = 0;   KX = 32; t = b - 704; }
    else               { src = W4ls; dst = Wt4; Ns = 512;  Kd = 1024; n_off = 512; KX = 32; t = b - 1216; }
    const int k0 = (t % KX) * 32, n0 = (t / KX) * 32;

    __shared__ float tile[32][33];
    for (int i = ty; i < 32; i += 8)
        tile[i][tx] = src[(size_t)(k0 + i) * Ns + n0 + tx];
    __syncthreads();
    for (int i = ty; i < 32; i += 8)
        dst[(size_t)(n_off + n0 + i) * Kd + k0 + tx] = __float2bfloat16(tile[tx][i]);
}

__global__ void conv_x(const float* __restrict__ x, bf16* __restrict__ xb) {
    size_t i = ((size_t)blockIdx.x * blockDim.x + threadIdx.x) * 8;
    float4 a = *(const float4*)(x + i);
    float4 b = *(const float4*)(x + i + 4);
    uint32_t p[4];
    __nv_bfloat162 t;
    t = __floats2bfloat162_rn(a.x, a.y); p[0] = *(uint32_t*)&t;
    t = __floats2bfloat162_rn(a.z, a.w); p[1] = *(uint32_t*)&t;
    t = __floats2bfloat162_rn(b.x, b.y); p[2] = *(uint32_t*)&t;
    t = __floats2bfloat162_rn(b.z, b.w); p[3] = *(uint32_t*)&t;
    *(uint4*)(xb + i) = *(uint4*)p;
}

// ---------------- per-row softmax + likelihood (all bf16 inputs) ------------
__global__ void row_loss(const bf16* __restrict__ out4, const bf16* __restrict__ xb,
                         const float* __restrict__ kl, float* __restrict__ rowout) {
    const int row = blockIdx.x;
    const int t = threadIdx.x;
    __shared__ float sh[8];
    const bf16* lr = out4 + (size_t)row * (2 * DIN);
    const bf16* vr = lr + DIN;
    float l0 = __bfloat162float(lr[t]), l1 = __bfloat162float(lr[t + 256]);

    float m = fmaxf(l0, l1);
#pragma unroll
    for (int o = 16; o > 0; o >>= 1) m = fmaxf(m, __shfl_xor_sync(0xffffffffu, m, o));
    if ((t & 31) == 0) sh[t >> 5] = m;
    __syncthreads();
    m = sh[0];
#pragma unroll
    for (int w = 1; w < 8; w++) m = fmaxf(m, sh[w]);
    __syncthreads();

    float e0 = expf(l0 - m), e1 = expf(l1 - m);
    float s = e0 + e1;
#pragma unroll
    for (int o = 16; o > 0; o >>= 1) s += __shfl_xor_sync(0xffffffffu, s, o);
    if ((t & 31) == 0) sh[t >> 5] = s;
    __syncthreads();
    s = 0.0f;
#pragma unroll
    for (int w = 0; w < 8; w++) s += sh[w];
    __syncthreads();
    float inv = 1.0f / s;

    const bf16* xr = xb + (size_t)row * DIN;
    float acc = 0.0f;
    {
        float p = e0 * inv, xv = __bfloat162float(xr[t]);
        float lv = __bfloat162float(vr[t]);
        float d = xv - p;
        acc += lv + d * d * expf(-lv);
        p = e1 * inv; xv = __bfloat162float(xr[t + 256]);
        lv = __bfloat162float(vr[t + 256]);
        d = xv - p;
        acc += lv + d * d * expf(-lv);
    }
#pragma unroll
    for (int o = 16; o > 0; o >>= 1) acc += __shfl_xor_sync(0xffffffffu, acc, o);
    if ((t & 31) == 0) sh[t >> 5] = acc;
    __syncthreads();
    if (t == 0) {
        float tot = 0.0f;
#pragma unroll
        for (int w = 0; w < 8; w++) tot += sh[w];
        float ln_pxz = -0.5f * (tot + (float)DIN * LOG2PI);
        rowout[row] = ln_pxz - kl[row];
    }
}

// ---------------- deterministic mean ----------------------------------------
__global__ void reduce_partial(const float* __restrict__ in, float* __restrict__ part) {
    const int t = threadIdx.x;
    __shared__ float sh[8];
    float v = in[blockIdx.x * 256 + t];
#pragma unroll
    for (int o = 16; o > 0; o >>= 1) v += __shfl_xor_sync(0xffffffffu, v, o);
    if ((t & 31) == 0) sh[t >> 5] = v;
    __syncthreads();
    if (t == 0) {
        float s = 0.0f;
#pragma unroll
        for (int w = 0; w < 8; w++) s += sh[w];
        part[blockIdx.x] = s;
    }
}
__global__ void reduce_final(const float* __restrict__ part, float* __restrict__ out) {
    const int t = threadIdx.x;
    __shared__ float sh[8];
    float v = part[t];
#pragma unroll
    for (int o = 16; o > 0; o >>= 1) v += __shfl_xor_sync(0xffffffffu, v, o);
    if ((t & 31) == 0) sh[t >> 5] = v;
    __syncthreads();
    if (t == 0) {
        float s = 0.0f;
#pragma unroll
        for (int w = 0; w < 8; w++) s += sh[w];
        out[0] = s * (1.0f / (float)BATCH);
    }
}

// ---------------- launch ----------------------------------------------------
extern "C" void kernel_launch(void* const* d_in, const int* in_sizes, int n_in,
                              void* d_out, int out_size) {
    const float* x        = (const float*)d_in[0];
    const float* eps      = (const float*)d_in[1];
    const float* W_enc_h  = (const float*)d_in[2];
    const float* b_enc_h  = (const float*)d_in[3];
    const float* W_enc_mu = (const float*)d_in[4];
    const float* b_enc_mu = (const float*)d_in[5];
    const float* W_enc_lv = (const float*)d_in[6];
    const float* b_enc_lv = (const float*)d_in[7];
    const float* W_dec_h  = (const float*)d_in[8];
    const float* b_dec_h  = (const float*)d_in[9];
    const float* W_dec_mu = (const float*)d_in[10];
    const float* b_dec_mu = (const float*)d_in[11];
    const float* W_dec_lv = (const float*)d_in[12];
    const float* b_dec_lv = (const float*)d_in[13];
    float* out = (float*)d_out;

    bf16 *p_xb, *p_h, *p_out4, *p_Wt1, *p_Wt2, *p_Wt3, *p_Wt4;
    float *p_kl, *p_row, *p_part, *p_b2, *p_b4;
    cudaGetSymbolAddress((void**)&p_xb, sc_xb);
    cudaGetSymbolAddress((void**)&p_h, sc_h);
    cudaGetSymbolAddress((void**)&p_out4, sc_out4);
    cudaGetSymbolAddress((void**)&p_kl, sc_kl);
    cudaGetSymbolAddress((void**)&p_row, sc_row);
    cudaGetSymbolAddress((void**)&p_part, sc_part);
    cudaGetSymbolAddress((void**)&p_Wt1, sc_Wt1);
    cudaGetSymbolAddress((void**)&p_Wt2, sc_Wt2);
    cudaGetSymbolAddress((void**)&p_Wt3, sc_Wt3);
    cudaGetSymbolAddress((void**)&p_Wt4, sc_Wt4);
    cudaGetSymbolAddress((void**)&p_b2, sc_b2);
    cudaGetSymbolAddress((void**)&p_b4, sc_b4);

    cudaFuncSetAttribute(gemm_mma<0>, cudaFuncAttributeMaxDynamicSharedMemorySize, SMEMSZ);
    cudaFuncSetAttribute(gemm_mma<1>, cudaFuncAttributeMaxDynamicSharedMemorySize, SMEMSZ);
    cudaFuncSetAttribute(enc23,       cudaFuncAttributeMaxDynamicSharedMemorySize, SMEMSZ);

    // prep (2 launches)
    conv_x<<<(BATCH * DIN) / (256 * 8), 256>>>(x, p_xb);
    prep_weights<<<1729, dim3(32, 8)>>>(W_enc_h, W_enc_mu, W_enc_lv, W_dec_h,
                                        W_dec_mu, W_dec_lv,
                                        p_Wt1, p_Wt2, p_Wt3, p_Wt4,
                                        b_enc_mu, b_enc_lv, b_dec_mu, b_dec_lv,
                                        p_b2, p_b4);

    // 1) h = tanh(x @ W1)
    gemm_mma<1><<<dim3(8, 512), 256, SMEMSZ>>>(p_xb, DIN, p_Wt1, b_enc_h, p_h, HID);
    // 2+3) enc head -> z (smem), kl; hd = tanh(z @ W3)
    enc23<<<BATCH / 128, 256, SMEMSZ>>>(p_h, p_Wt2, p_b2, eps, p_kl, p_Wt3, b_dec_h, p_h);
    // 4) logits|lvx = hd @ W4 (bf16 out)
    gemm_mma<0><<<dim3(8, 512), 256, SMEMSZ>>>(p_h, HID, p_Wt4, p_b4, p_out4, 2 * DIN);
    // 5) per-row loss, 6) deterministic mean
    row_loss<<<BATCH, 256>>>(p_out4, p_xb, p_kl, p_row);
    reduce_partial<<<256, 256>>>(p_row, p_part);
    reduce_final<<<1, 256>>>(p_part, out);
}

// round 17
// speedup vs baseline: 2.0793x; 1.1407x over previous
#include <cuda_runtime.h>
#include <cuda_bf16.h>
#include <cstdint>
#include <cstddef>

#define BATCH 65536
#define DIN   512
#define HID   1024
#define LAT   64
#define LOG2PI 1.8378770664093453f

typedef __nv_bfloat16 bf16;

// ---------------- scratch (__device__ globals; allocation-free rule) --------
__device__ bf16  sc_xb[(size_t)BATCH * DIN];        // x bf16             64MB
__device__ bf16  sc_h [(size_t)BATCH * HID];        // h / hd bf16       128MB
__device__ bf16  sc_out4[(size_t)BATCH * (2*DIN)];  // logits|lvx bf16   128MB
__device__ float sc_kl[BATCH];
__device__ float sc_row[BATCH];
__device__ float sc_part[256];
__device__ bf16  sc_Wt1[(size_t)HID * DIN];
__device__ bf16  sc_Wt2[(size_t)(2*LAT) * HID];
__device__ bf16  sc_Wt3[(size_t)HID * LAT];
__device__ bf16  sc_Wt4[(size_t)(2*DIN) * HID];
__device__ float sc_b2[2*LAT];
__device__ float sc_b4[2*DIN];

// ---------------- helpers ---------------------------------------------------
__device__ __forceinline__ uint32_t smem_u32(const void* p) {
    uint32_t a;
    asm("{ .reg .u64 t; cvta.to.shared.u64 t, %1; cvt.u32.u64 %0, t; }" : "=r"(a) : "l"(p));
    return a;
}
#define SWZ(off) ((off) ^ (((off) >> 3) & 0x70))

__device__ __forceinline__ float ftanh(float x) {
    float y;
    asm("tanh.approx.f32 %0, %1;" : "=f"(y) : "f"(x));
    return y;
}

__device__ __forceinline__ void cp16(uint32_t dst, const void* src) {
    asm volatile("cp.async.cg.shared.global.L2::256B [%0], [%1], 16;" :: "r"(dst), "l"(src));
}
#define CP_COMMIT() asm volatile("cp.async.commit_group;" ::: "memory")
#define CP_WAIT(n)  asm volatile("cp.async.wait_group %0;" :: "n"(n) : "memory")

__device__ __forceinline__ void ldmX4(uint32_t& a0, uint32_t& a1, uint32_t& a2, uint32_t& a3,
                                      uint32_t addr) {
    asm volatile("ldmatrix.sync.aligned.m8n8.x4.shared.b16 {%0,%1,%2,%3}, [%4];"
                 : "=r"(a0), "=r"(a1), "=r"(a2), "=r"(a3) : "r"(addr));
}
__device__ __forceinline__ void mma16816(float& c0, float& c1, float& c2, float& c3,
                                         uint32_t a0, uint32_t a1, uint32_t a2, uint32_t a3,
                                         uint32_t b0, uint32_t b1) {
    asm volatile("mma.sync.aligned.m16n8k16.row.col.f32.bf16.bf16.f32 "
                 "{%0,%1,%2,%3}, {%4,%5,%6,%7}, {%8,%9}, {%0,%1,%2,%3};"
                 : "+f"(c0), "+f"(c1), "+f"(c2), "+f"(c3)
                 : "r"(a0), "r"(a1), "r"(a2), "r"(a3), "r"(b0), "r"(b1));
}

// ---------------- tile prefetch: 128 rows x 64 bf16, SW128, cp.async --------
__device__ __forceinline__ void prefetch_tile(const bf16* __restrict__ g, int pitch,
                                              int row0, int kofs, uint32_t sbase, int tid) {
#pragma unroll
    for (int u = 0; u < 4; u++) {
        int id  = tid + u * 256;
        int r   = id >> 3;
        int c16 = id & 7;
        uint32_t off = (uint32_t)(r * 128 + c16 * 16);
        cp16(sbase + SWZ(off), g + (size_t)(row0 + r) * pitch + kofs + c16 * 8);
    }
}

// ---------------- mma.sync GEMM: D = A[M,K] @ Bt[N,K]^T ---------------------
// block tile 128x128, BK=64, 256 threads (8 warps, 2x4), warp tile 64x32.
// 3-stage cp.async ring, ONE barrier per K-iteration, 2 CTAs/SM enforced.
// EPI: 0 = bias + bf16 store, 1 = bias+tanh+bf16 store
static constexpr int PAD = 130;
static constexpr int STAGE = 32768;
static constexpr int SMEMSZ = 3 * STAGE;

template<int EPI>
__global__ __launch_bounds__(256, 2) void gemm_mma(
    const bf16* __restrict__ A, int Ka,
    const bf16* __restrict__ Bt,
    const float* __restrict__ bias,
    bf16* __restrict__ Cout, int Np)
{
    extern __shared__ char smem[];
    const uint32_t sb = smem_u32(smem);
    const int tid = threadIdx.x, wid = tid >> 5, lane = tid & 31;
    const int wm = wid >> 2, wn = wid & 3;
    const int row0 = blockIdx.y * 128, col0 = blockIdx.x * 128;

    float c[4][4][4];
#pragma unroll
    for (int i = 0; i < 4; i++)
#pragma unroll
        for (int j = 0; j < 4; j++)
#pragma unroll
            for (int q = 0; q < 4; q++) c[i][j][q] = 0.0f;

    const int KT = Ka / 64;
    prefetch_tile(A,  Ka, row0, 0, sb, tid);
    prefetch_tile(Bt, Ka, col0, 0, sb + 16384, tid);
    CP_COMMIT();
    if (KT > 1) {
        prefetch_tile(A,  Ka, row0, 64, sb + STAGE, tid);
        prefetch_tile(Bt, Ka, col0, 64, sb + STAGE + 16384, tid);
    }
    CP_COMMIT();

    const int arow = wm * 64 + (lane & 15);
    const uint32_t acol = ((uint32_t)(lane >> 4)) << 4;
    const int g = lane >> 3;
    const int bRowBase = wn * 32 + (g >> 1) * 8 + (lane & 7);
    const uint32_t bColHalf = (uint32_t)(g & 1) << 4;

    int stage = 0;
    for (int kt = 0; kt < KT; kt++) {
        CP_WAIT(1);
        __syncthreads();
        {
            int pf = kt + 2;
            int pstage = stage + 2; if (pstage >= 3) pstage -= 3;
            if (pf < KT) {
                prefetch_tile(A,  Ka, row0, pf * 64, sb + pstage * STAGE, tid);
                prefetch_tile(Bt, Ka, col0, pf * 64, sb + pstage * STAGE + 16384, tid);
            }
            CP_COMMIT();
        }
        const uint32_t SAb = sb + stage * STAGE;
        const uint32_t SBb = SAb + 16384;
#pragma unroll
        for (int ks = 0; ks < 4; ks++) {
            uint32_t af[4][4], bfr[4][2];
#pragma unroll
            for (int i = 0; i < 4; i++) {
                uint32_t off = (uint32_t)((arow + i * 16) * 128) + ks * 32 + acol;
                ldmX4(af[i][0], af[i][1], af[i][2], af[i][3], SAb + SWZ(off));
            }
#pragma unroll
            for (int jp = 0; jp < 2; jp++) {
                uint32_t off = (uint32_t)((bRowBase + jp * 16) * 128) + ks * 32 + bColHalf;
                ldmX4(bfr[jp*2][0], bfr[jp*2][1], bfr[jp*2+1][0], bfr[jp*2+1][1],
                      SBb + SWZ(off));
            }
#pragma unroll
            for (int i = 0; i < 4; i++)
#pragma unroll
                for (int j = 0; j < 4; j++)
                    mma16816(c[i][j][0], c[i][j][1], c[i][j][2], c[i][j][3],
                             af[i][0], af[i][1], af[i][2], af[i][3],
                             bfr[j][0], bfr[j][1]);
        }
        if (++stage == 3) stage = 0;
    }

    __syncthreads();
    float* stg = (float*)smem;
    {
        const int r0 = wm * 64 + (lane >> 2);
        const int cfix = wn * 32 + (lane & 3) * 2;
#pragma unroll
        for (int i = 0; i < 4; i++)
#pragma unroll
            for (int j = 0; j < 4; j++) {
                int sr = r0 + i * 16, scol = cfix + j * 8;
                stg[sr * PAD + scol]           = c[i][j][0];
                stg[sr * PAD + scol + 1]       = c[i][j][1];
                stg[(sr + 8) * PAD + scol]     = c[i][j][2];
                stg[(sr + 8) * PAD + scol + 1] = c[i][j][3];
            }
    }
    __syncthreads();

#pragma unroll
    for (int it = 0; it < 16; it++) {
        int id = tid + it * 256;
        int row = id >> 5, col = (id & 31) * 4;
        float v0 = stg[row * PAD + col]     + bias[col0 + col];
        float v1 = stg[row * PAD + col + 1] + bias[col0 + col + 1];
        float v2 = stg[row * PAD + col + 2] + bias[col0 + col + 2];
        float v3 = stg[row * PAD + col + 3] + bias[col0 + col + 3];
        if (EPI == 1) { v0 = ftanh(v0); v1 = ftanh(v1); v2 = ftanh(v2); v3 = ftanh(v3); }
        __nv_bfloat162 t0 = __floats2bfloat162_rn(v0, v1);
        __nv_bfloat162 t1 = __floats2bfloat162_rn(v2, v3);
        uint2 o = make_uint2(*(uint32_t*)&t0, *(uint32_t*)&t1);
        *(uint2*)(Cout + (size_t)(row0 + row) * Np + col0 + col) = o;
    }
}

// ---------------- enc23: GEMM2 (enc head) + GEMM3 fused ---------------------
// smem layout (99328 B, 2 CTAs/SM):
//   phase1 ring: 3 x 32KB at [0, 98304)
//   stg:   [0, 66560)          (after phase-1 mainloop)
//   Bt3 t0:[66560, 82944)      (prefetched during epilogue)
//   z:     [82944, 99328)      (bf16 SW128)
//   phase3 B ring: 3 x 16KB at [0, 49152)
static constexpr int T0OFF = 66560;
static constexpr int ZOFF  = 82944;
static constexpr int SMEMSZ_E = 99328;

__global__ __launch_bounds__(256, 2) void enc23(
    const bf16* __restrict__ A,        // h [B,1024]
    const bf16* __restrict__ Bt2,      // Wt2 [128,1024]
    const float* __restrict__ b2,      // [128]
    const float* __restrict__ eps,     // [B,64] fp32
    float* __restrict__ klout,         // [B]
    const bf16* __restrict__ Bt3,      // Wt3 [1024,64]
    const float* __restrict__ b3,      // [1024]
    bf16* __restrict__ Cout)           // hd [B,1024]
{
    extern __shared__ char smem[];
    const uint32_t sb = smem_u32(smem);
    const int tid = threadIdx.x, wid = tid >> 5, lane = tid & 31;
    const int wm = wid >> 2, wn = wid & 3;
    const int row0 = blockIdx.x * 128;

    const int arow = wm * 64 + (lane & 15);
    const uint32_t acol = ((uint32_t)(lane >> 4)) << 4;
    const int g = lane >> 3;
    const int bRowBase = wn * 32 + (g >> 1) * 8 + (lane & 7);
    const uint32_t bColHalf = (uint32_t)(g & 1) << 4;

    // ================= phase 1: GEMM2 =================
    {
        float c[4][4][4];
#pragma unroll
        for (int i = 0; i < 4; i++)
#pragma unroll
            for (int j = 0; j < 4; j++)
#pragma unroll
                for (int q = 0; q < 4; q++) c[i][j][q] = 0.0f;

        prefetch_tile(A,   HID, row0, 0, sb, tid);
        prefetch_tile(Bt2, HID, 0,    0, sb + 16384, tid);
        CP_COMMIT();
        prefetch_tile(A,   HID, row0, 64, sb + STAGE, tid);
        prefetch_tile(Bt2, HID, 0,    64, sb + STAGE + 16384, tid);
        CP_COMMIT();

        int stage = 0;
        for (int kt = 0; kt < 16; kt++) {
            CP_WAIT(1);
            __syncthreads();
            {
                int pf = kt + 2;
                int pstage = stage + 2; if (pstage >= 3) pstage -= 3;
                if (pf < 16) {
                    prefetch_tile(A,   HID, row0, pf * 64, sb + pstage * STAGE, tid);
                    prefetch_tile(Bt2, HID, 0,    pf * 64, sb + pstage * STAGE + 16384, tid);
                }
                CP_COMMIT();
            }
            const uint32_t SAb = sb + stage * STAGE;
            const uint32_t SBb = SAb + 16384;
#pragma unroll
            for (int ks = 0; ks < 4; ks++) {
                uint32_t af[4][4], bfr[4][2];
#pragma unroll
                for (int i = 0; i < 4; i++) {
                    uint32_t off = (uint32_t)((arow + i * 16) * 128) + ks * 32 + acol;
                    ldmX4(af[i][0], af[i][1], af[i][2], af[i][3], SAb + SWZ(off));
                }
#pragma unroll
                for (int jp = 0; jp < 2; jp++) {
                    uint32_t off = (uint32_t)((bRowBase + jp * 16) * 128) + ks * 32 + bColHalf;
                    ldmX4(bfr[jp*2][0], bfr[jp*2][1], bfr[jp*2+1][0], bfr[jp*2+1][1],
                          SBb + SWZ(off));
                }
#pragma unroll
                for (int i = 0; i < 4; i++)
#pragma unroll
                    for (int j = 0; j < 4; j++)
                        mma16816(c[i][j][0], c[i][j][1], c[i][j][2], c[i][j][3],
                                 af[i][0], af[i][1], af[i][2], af[i][3],
                                 bfr[j][0], bfr[j][1]);
            }
            if (++stage == 3) stage = 0;
        }

        __syncthreads();
        float* stg = (float*)smem;
        {
            const int r0 = wm * 64 + (lane >> 2);
            const int cfix = wn * 32 + (lane & 3) * 2;
#pragma unroll
            for (int i = 0; i < 4; i++)
#pragma unroll
                for (int j = 0; j < 4; j++) {
                    int sr = r0 + i * 16, scol = cfix + j * 8;
                    stg[sr * PAD + scol]           = c[i][j][0];
                    stg[sr * PAD + scol + 1]       = c[i][j][1];
                    stg[(sr + 8) * PAD + scol]     = c[i][j][2];
                    stg[(sr + 8) * PAD + scol + 1] = c[i][j][3];
                }
        }
        // overlap: prefetch phase-3 B tile0 into T0OFF (disjoint from stg & z)
        prefetch_tile(Bt3, LAT, 0, 0, sb + T0OFF, tid);
        CP_COMMIT();
        __syncthreads();

        // epilogue: mu/lv -> z (smem bf16 SW128 @ ZOFF), KL
        if (tid < 128) {
            const int row = tid;
            const int r = row0 + row;
            float klacc = 0.0f;
            uint32_t zp[32];
            const float* er = eps + (size_t)r * LAT;
#pragma unroll
            for (int j = 0; j < 64; j += 2) {
                float mu0 = stg[row * PAD + j]     + b2[j];
                float mu1 = stg[row * PAD + j + 1] + b2[j + 1];
                float lv0 = stg[row * PAD + 64 + j]     + b2[64 + j];
                float lv1 = stg[row * PAD + 64 + j + 1] + b2[64 + j + 1];
                float z0 = fmaf(__expf(0.5f * lv0), er[j],     mu0);
                float z1 = fmaf(__expf(0.5f * lv1), er[j + 1], mu1);
                klacc += (1.0f + lv0 - mu0 * mu0 - __expf(lv0));
                klacc += (1.0f + lv1 - mu1 * mu1 - __expf(lv1));
                __nv_bfloat162 t = __floats2bfloat162_rn(z0, z1);
                zp[j >> 1] = *(uint32_t*)&t;
            }
#pragma unroll
            for (int q = 0; q < 8; q++) {
                uint32_t off = (uint32_t)(row * 128 + q * 16);
                *(uint4*)(smem + ZOFF + SWZ(off)) = ((uint4*)zp)[q];
            }
            klout[r] = -0.5f * klacc;
        }
        __syncthreads();
    }

    // ================= phase 3: GEMM3 (A = z in smem) =================
    {
        const uint32_t SAz = sb + ZOFF;
        // t0 already committed (into T0OFF); prefetch t1 into ring slot 0
        prefetch_tile(Bt3, LAT, 128, 0, sb, tid);
        CP_COMMIT();

        const int fr0 = wm * 64 + (lane >> 2);
        const int fc0 = wn * 32 + (lane & 3) * 2;

        for (int nt = 0; nt < 8; nt++) {
            CP_WAIT(1);
            __syncthreads();
            {
                int pf = nt + 2;
                if (pf < 8) prefetch_tile(Bt3, LAT, pf * 128, 0,
                                          sb + ((pf - 1) % 3) * 16384, tid);
                CP_COMMIT();
            }
            const uint32_t SBb = (nt == 0) ? (sb + T0OFF)
                                           : (sb + ((nt - 1) % 3) * 16384);
            float c[4][4][4];
#pragma unroll
            for (int i = 0; i < 4; i++)
#pragma unroll
                for (int j = 0; j < 4; j++)
#pragma unroll
                    for (int q = 0; q < 4; q++) c[i][j][q] = 0.0f;
#pragma unroll
            for (int ks = 0; ks < 4; ks++) {
                uint32_t af[4][4], bfr[4][2];
#pragma unroll
                for (int i = 0; i < 4; i++) {
                    uint32_t off = (uint32_t)((arow + i * 16) * 128) + ks * 32 + acol;
                    ldmX4(af[i][0], af[i][1], af[i][2], af[i][3], SAz + SWZ(off));
                }
#pragma unroll
                for (int jp = 0; jp < 2; jp++) {
                    uint32_t off = (uint32_t)((bRowBase + jp * 16) * 128) + ks * 32 + bColHalf;
                    ldmX4(bfr[jp*2][0], bfr[jp*2][1], bfr[jp*2+1][0], bfr[jp*2+1][1],
                          SBb + SWZ(off));
                }
#pragma unroll
                for (int i = 0; i < 4; i++)
#pragma unroll
                    for (int j = 0; j < 4; j++)
                        mma16816(c[i][j][0], c[i][j][1], c[i][j][2], c[i][j][3],
                                 af[i][0], af[i][1], af[i][2], af[i][3],
                                 bfr[j][0], bfr[j][1]);
            }
            const int col0 = nt * 128;
#pragma unroll
            for (int i = 0; i < 4; i++)
#pragma unroll
                for (int j = 0; j < 4; j++) {
                    int sc = col0 + fc0 + j * 8;
                    float b0 = b3[sc], b1 = b3[sc + 1];
                    int r = row0 + fr0 + i * 16;
                    __nv_bfloat162 t0 = __floats2bfloat162_rn(ftanh(c[i][j][0] + b0),
                                                              ftanh(c[i][j][1] + b1));
                    __nv_bfloat162 t1 = __floats2bfloat162_rn(ftanh(c[i][j][2] + b0),
                                                              ftanh(c[i][j][3] + b1));
                    *(uint32_t*)(Cout + (size_t)r * HID + sc)       = *(uint32_t*)&t0;
                    *(uint32_t*)(Cout + (size_t)(r + 8) * HID + sc) = *(uint32_t*)&t1;
                }
        }
    }
}

// ---------------- fused prep: transposes + biases + x conversion ------------
// grid 18113 x (32,8):
//  [0,512)     W_enc_h  -> Wt1   [512,576) W_enc_mu -> Wt2   [576,640) W_enc_lv
//  [640,704)   W_dec_h  -> Wt3   [704,1216) W_dec_mu -> Wt4  [1216,1728) W_dec_lv
//  1728        biases
//  [1729,18113) conv x -> xb (2048 elems per block)
__global__ void prep_all(
    const float* __restrict__ x, bf16* __restrict__ xb,
    const float* __restrict__ W1s, const float* __restrict__ W2ms,
    const float* __restrict__ W2ls, const float* __restrict__ W3s,
    const float* __restrict__ W4ms, const float* __restrict__ W4ls,
    bf16* __restrict__ Wt1, bf16* __restrict__ Wt2,
    bf16* __restrict__ Wt3, bf16* __restrict__ Wt4,
    const float* __restrict__ bemu, const float* __restrict__ belv,
    const float* __restrict__ bdmu, const float* __restrict__ bdlv,
    float* __restrict__ pb2, float* __restrict__ pb4)
{
    const int b = blockIdx.x;
    const int tx = threadIdx.x, ty = threadIdx.y;
    const int tid = ty * 32 + tx;
    if (b >= 1729) {
        size_t i = ((size_t)(b - 1729) * 256 + tid) * 8;
        float4 a = *(const float4*)(x + i);
        float4 bb = *(const float4*)(x + i + 4);
        uint32_t p[4];
        __nv_bfloat162 t;
        t = __floats2bfloat162_rn(a.x, a.y);  p[0] = *(uint32_t*)&t;
        t = __floats2bfloat162_rn(a.z, a.w);  p[1] = *(uint32_t*)&t;
        t = __floats2bfloat162_rn(bb.x, bb.y); p[2] = *(uint32_t*)&t;
        t = __floats2bfloat162_rn(bb.z, bb.w); p[3] = *(uint32_t*)&t;
        *(uint4*)(xb + i) = *(uint4*)p;
        return;
    }
    if (b == 1728) {
        if (tid < 64) pb2[tid] = bemu[tid];
        else if (tid < 128) pb2[tid] = belv[tid - 64];
        for (int i = tid; i < 512; i += 256) {
            pb4[i] = bdmu[i];
            pb4[512 + i] = bdlv[i];
        }
        return;
    }
    const float* src; bf16* dst; int Ns, Kd, n_off, KX, t;
    if (b < 512)       { src = W1s;  dst = Wt1; Ns = 1024; Kd = 512;  n_off = 0;   KX = 16; t = b; }
    else if (b < 576)  { src = W2ms; dst = Wt2; Ns = 64;   Kd = 1024; n_off = 0;   KX = 32; t = b - 512; }
    else if (b < 640)  { src = W2ls; dst = Wt2; Ns = 64;   Kd = 1024; n_off = 64;  KX = 32; t = b - 576; }
    else if (b < 704)  { src = W3s;  dst = Wt3; Ns = 1024; Kd = 64;   n_off = 0;   KX = 2;  t = b - 640; }
    else if (b < 1216) { src = W4ms; dst = Wt4; Ns = 512;  Kd = 1024; n_off = 0;   KX = 32; t = b - 704; }
    else               { src = W4ls; dst = Wt4; Ns = 512;  Kd = 1024; n_off = 512; KX = 32; t = b - 1216; }
    const int k0 = (t % KX) * 32, n0 = (t / KX) * 32;

    __shared__ float tile[32][33];
    for (int i = ty; i < 32; i += 8)
        tile[i][tx] = src[(size_t)(k0 + i) * Ns + n0 + tx];
    __syncthreads();
    for (int i = ty; i < 32; i += 8)
        dst[(size_t)(n_off + n0 + i) * Kd + k0 + tx] = __float2bfloat16(tile[tx][i]);
}

// ---------------- per-row softmax + likelihood: warp-per-row ----------------
// 8 rows/block, grid = BATCH/8. Coalesced uint2 loads, butterfly reductions
// (commutative pairwise adds -> bitwise-identical on all lanes, deterministic).
__global__ __launch_bounds__(256) void row_loss(
    const bf16* __restrict__ out4, const bf16* __restrict__ xb,
    const float* __restrict__ kl, float* __restrict__ rowout)
{
    const int wid = threadIdx.x >> 5, lane = threadIdx.x & 31;
    const int row = blockIdx.x * 8 + wid;
    const bf16* lr = out4 + (size_t)row * (2 * DIN);
    const bf16* vr = lr + DIN;
    const bf16* xr = xb + (size_t)row * DIN;

    // load 16 logits: chunk k, elems [4*lane + 128*k, +4)
    float l[16];
#pragma unroll
    for (int k = 0; k < 4; k++) {
        uint2 v = *(const uint2*)(lr + lane * 4 + k * 128);
        __nv_bfloat162 b0 = *(__nv_bfloat162*)&v.x;
        __nv_bfloat162 b1 = *(__nv_bfloat162*)&v.y;
        l[k*4+0] = __bfloat162float(b0.x); l[k*4+1] = __bfloat162float(b0.y);
        l[k*4+2] = __bfloat162float(b1.x); l[k*4+3] = __bfloat162float(b1.y);
    }
    float m = l[0];
#pragma unroll
    for (int q = 1; q < 16; q++) m = fmaxf(m, l[q]);
#pragma unroll
    for (int o = 16; o > 0; o >>= 1) m = fmaxf(m, __shfl_xor_sync(0xffffffffu, m, o));

    float s = 0.0f;
#pragma unroll
    for (int q = 0; q < 16; q++) { l[q] = __expf(l[q] - m); s += l[q]; }
#pragma unroll
    for (int o = 16; o > 0; o >>= 1) s += __shfl_xor_sync(0xffffffffu, s, o);
    const float inv = 1.0f / s;

    float acc = 0.0f;
#pragma unroll
    for (int k = 0; k < 4; k++) {
        uint2 vv = *(const uint2*)(vr + lane * 4 + k * 128);
        uint2 xv = *(const uint2*)(xr + lane * 4 + k * 128);
        __nv_bfloat162 v0 = *(__nv_bfloat162*)&vv.x, v1 = *(__nv_bfloat162*)&vv.y;
        __nv_bfloat162 x0 = *(__nv_bfloat162*)&xv.x, x1 = *(__nv_bfloat162*)&xv.y;
        float lv[4] = { __bfloat162float(v0.x), __bfloat162float(v0.y),
                        __bfloat162float(v1.x), __bfloat162float(v1.y) };
        float xf[4] = { __bfloat162float(x0.x), __bfloat162float(x0.y),
                        __bfloat162float(x1.x), __bfloat162float(x1.y) };
#pragma unroll
        for (int q = 0; q < 4; q++) {
            float p = l[k*4+q] * inv;
            float d = xf[q] - p;
            acc += lv[q] + d * d * __expf(-lv[q]);
        }
    }
#pragma unroll
    for (int o = 16; o > 0; o >>= 1) acc += __shfl_xor_sync(0xffffffffu, acc, o);
    if (lane == 0) {
        float ln_pxz = -0.5f * (acc + (float)DIN * LOG2PI);
        rowout[row] = ln_pxz - kl[row];
    }
}

// ---------------- deterministic mean ----------------------------------------
__global__ void reduce_partial(const float* __restrict__ in, float* __restrict__ part) {
    const int t = threadIdx.x;
    __shared__ float sh[8];
    float v = in[blockIdx.x * 256 + t];
#pragma unroll
    for (int o = 16; o > 0; o >>= 1) v += __shfl_xor_sync(0xffffffffu, v, o);
    if ((t & 31) == 0) sh[t >> 5] = v;
    __syncthreads();
    if (t == 0) {
        float s = 0.0f;
#pragma unroll
        for (int w = 0; w < 8; w++) s += sh[w];
        part[blockIdx.x] = s;
    }
}
__global__ void reduce_final(const float* __restrict__ part, float* __restrict__ out) {
    const int t = threadIdx.x;
    __shared__ float sh[8];
    float v = part[t];
#pragma unroll
    for (int o = 16; o > 0; o >>= 1) v += __shfl_xor_sync(0xffffffffu, v, o);
    if ((t & 31) == 0) sh[t >> 5] = v;
    __syncthreads();
    if (t == 0) {
        float s = 0.0f;
#pragma unroll
        for (int w = 0; w < 8; w++) s += sh[w];
        out[0] = s * (1.0f / (float)BATCH);
    }
}

// ---------------- launch ----------------------------------------------------
extern "C" void kernel_launch(void* const* d_in, const int* in_sizes, int n_in,
                              void* d_out, int out_size) {
    const float* x        = (const float*)d_in[0];
    const float* eps      = (const float*)d_in[1];
    const float* W_enc_h  = (const float*)d_in[2];
    const float* b_enc_h  = (const float*)d_in[3];
    const float* W_enc_mu = (const float*)d_in[4];
    const float* b_enc_mu = (const float*)d_in[5];
    const float* W_enc_lv = (const float*)d_in[6];
    const float* b_enc_lv = (const float*)d_in[7];
    const float* W_dec_h  = (const float*)d_in[8];
    const float* b_dec_h  = (const float*)d_in[9];
    const float* W_dec_mu = (const float*)d_in[10];
    const float* b_dec_mu = (const float*)d_in[11];
    const float* W_dec_lv = (const float*)d_in[12];
    const float* b_dec_lv = (const float*)d_in[13];
    float* out = (float*)d_out;

    bf16 *p_xb, *p_h, *p_out4, *p_Wt1, *p_Wt2, *p_Wt3, *p_Wt4;
    float *p_kl, *p_row, *p_part, *p_b2, *p_b4;
    cudaGetSymbolAddress((void**)&p_xb, sc_xb);
    cudaGetSymbolAddress((void**)&p_h, sc_h);
    cudaGetSymbolAddress((void**)&p_out4, sc_out4);
    cudaGetSymbolAddress((void**)&p_kl, sc_kl);
    cudaGetSymbolAddress((void**)&p_row, sc_row);
    cudaGetSymbolAddress((void**)&p_part, sc_part);
    cudaGetSymbolAddress((void**)&p_Wt1, sc_Wt1);
    cudaGetSymbolAddress((void**)&p_Wt2, sc_Wt2);
    cudaGetSymbolAddress((void**)&p_Wt3, sc_Wt3);
    cudaGetSymbolAddress((void**)&p_Wt4, sc_Wt4);
    cudaGetSymbolAddress((void**)&p_b2, sc_b2);
    cudaGetSymbolAddress((void**)&p_b4, sc_b4);

    cudaFuncSetAttribute(gemm_mma<0>, cudaFuncAttributeMaxDynamicSharedMemorySize, SMEMSZ);
    cudaFuncSetAttribute(gemm_mma<1>, cudaFuncAttributeMaxDynamicSharedMemorySize, SMEMSZ);
    cudaFuncSetAttribute(enc23,       cudaFuncAttributeMaxDynamicSharedMemorySize, SMEMSZ_E);

    // prep (single launch: transposes + biases + x conversion)
    prep_all<<<1729 + (BATCH * DIN) / 2048, dim3(32, 8)>>>(
        x, p_xb, W_enc_h, W_enc_mu, W_enc_lv, W_dec_h, W_dec_mu, W_dec_lv,
        p_Wt1, p_Wt2, p_Wt3, p_Wt4,
        b_enc_mu, b_enc_lv, b_dec_mu, b_dec_lv, p_b2, p_b4);

    // 1) h = tanh(x @ W1)
    gemm_mma<1><<<dim3(8, 512), 256, SMEMSZ>>>(p_xb, DIN, p_Wt1, b_enc_h, p_h, HID);
    // 2+3) enc head -> z (smem), kl; hd = tanh(z @ W3)
    enc23<<<BATCH / 128, 256, SMEMSZ_E>>>(p_h, p_Wt2, p_b2, eps, p_kl, p_Wt3, b_dec_h, p_h);
    // 4) logits|lvx = hd @ W4 (bf16 out)
    gemm_mma<0><<<dim3(8, 512), 256, SMEMSZ>>>(p_h, HID, p_Wt4, p_b4, p_out4, 2 * DIN);
    // 5) per-row loss, 6) deterministic mean
    row_loss<<<BATCH / 8, 256>>>(p_out4, p_xb, p_kl, p_row);
    reduce_partial<<<256, 256>>>(p_row, p_part);
    reduce_final<<<1, 256>>>(p_part, out);
}